// round 1
// baseline (speedup 1.0000x reference)
#include <cuda_runtime.h>
#include <cstdint>

#define NQ   14
#define NL   4
#define DIM  16384          // 2^14
#define NT   256            // threads per CTA
#define SEQL 8

// ---------------------------------------------------------------------------
// Shared-memory swizzle: phys = idx ^ ((idx>>5)&31).  Bijective (high bits
// unchanged), and because XOR is linear and cube-offset bits are disjoint from
// base bits, per-access swizzled offsets are compile-time constants.
// ---------------------------------------------------------------------------
__device__ __forceinline__ int swz(int i) { return i ^ ((i >> 5) & 31); }

template<int P> __device__ __forceinline__ int ins0(int v) {
    return ((v & ~((1 << P) - 1)) << 1) | (v & ((1 << P) - 1));
}
// insert zero bits at sorted-ascending positions -> cube base index
template<int B0,int B1,int B2,int B3,int B4>
__device__ __forceinline__ int expand5(int id) {
    int v = ins0<B0>(id); v = ins0<B1>(v); v = ins0<B2>(v);
    v = ins0<B3>(v);      v = ins0<B4>(v); return v;
}
template<int B0,int B1,int B2>
__device__ __forceinline__ int expand3(int id) {
    int v = ins0<B0>(id); v = ins0<B1>(v); v = ins0<B2>(v); return v;
}

// ---------------------------------------------------------------------------
// Register-cube primitives (fully unrolled; indices compile-time -> registers)
// ---------------------------------------------------------------------------
template<int NB, int J>
__device__ __forceinline__ void cube_gate(float2* a, const float* g) {
    const float4 gA = *(const float4*)g;        // u00.re,u00.im,u01.re,u01.im
    const float4 gB = *(const float4*)(g + 4);  // u10.re,u10.im,u11.re,u11.im
#pragma unroll
    for (int k = 0; k < (1 << NB); ++k)
        if (!(k & (1 << J))) {
            float2 p0 = a[k], p1 = a[k | (1 << J)];
            float2 n0, n1;
            n0.x = gA.x*p0.x - gA.y*p0.y + gA.z*p1.x - gA.w*p1.y;
            n0.y = gA.x*p0.y + gA.y*p0.x + gA.z*p1.y + gA.w*p1.x;
            n1.x = gB.x*p0.x - gB.y*p0.y + gB.z*p1.x - gB.w*p1.y;
            n1.y = gB.x*p0.y + gB.y*p0.x + gB.z*p1.y + gB.w*p1.x;
            a[k] = n0; a[k | (1 << J)] = n1;
        }
}

template<int NB, int JC, int JT>
__device__ __forceinline__ void cube_cnot(float2* a) {
#pragma unroll
    for (int k = 0; k < (1 << NB); ++k)
        if ((k & (1 << JC)) && !(k & (1 << JT))) {
            float2 t = a[k]; a[k] = a[k | (1 << JT)]; a[k | (1 << JT)] = t;
        }
}

template<int B0,int B1,int B2,int B3,int B4>
__device__ __forceinline__ void load32(float2* a, const float2* st, int pb) {
#pragma unroll
    for (int k = 0; k < 32; ++k) {
        int off = ((k&1)?(1<<B0):0) | ((k&2)?(1<<B1):0) | ((k&4)?(1<<B2):0)
                | ((k&8)?(1<<B3):0) | ((k&16)?(1<<B4):0);
        a[k] = st[pb ^ (off ^ ((off >> 5) & 31))];
    }
}
template<int B0,int B1,int B2,int B3,int B4>
__device__ __forceinline__ void store32(const float2* a, float2* st, int pb) {
#pragma unroll
    for (int k = 0; k < 32; ++k) {
        int off = ((k&1)?(1<<B0):0) | ((k&2)?(1<<B1):0) | ((k&4)?(1<<B2):0)
                | ((k&8)?(1<<B3):0) | ((k&16)?(1<<B4):0);
        st[pb ^ (off ^ ((off >> 5) & 31))] = a[k];
    }
}
template<int B0,int B1,int B2>
__device__ __forceinline__ void load8(float2* a, const float2* st, int pb) {
#pragma unroll
    for (int k = 0; k < 8; ++k) {
        int off = ((k&1)?(1<<B0):0) | ((k&2)?(1<<B1):0) | ((k&4)?(1<<B2):0);
        a[k] = st[pb ^ (off ^ ((off >> 5) & 31))];
    }
}
template<int B0,int B1,int B2>
__device__ __forceinline__ void store8(const float2* a, float2* st, int pb) {
#pragma unroll
    for (int k = 0; k < 8; ++k) {
        int off = ((k&1)?(1<<B0):0) | ((k&2)?(1<<B1):0) | ((k&4)?(1<<B2):0);
        st[pb ^ (off ^ ((off >> 5) & 31))] = a[k];
    }
}

__device__ __forceinline__ float2 cmul(float2 a, float2 b) {
    return make_float2(a.x*b.x - a.y*b.y, a.x*b.y + a.y*b.x);
}

// ---------------------------------------------------------------------------
// Kernel: one CTA per batch element. SMEM layout:
//   float2 st[16384]  (128 KB, swizzled)
//   float  gmat[4*14*8]  fused U = RZ*RY*RX per (layer, wire)
//   float  enc[14*2]     encoding cos/sin
//   float  red[126]      reduction scratch
// ---------------------------------------------------------------------------
__global__ void __launch_bounds__(NT, 1)
vqc_kernel(const float* __restrict__ x,   const float* __restrict__ w_in,
           const float* __restrict__ b_in,const float* __restrict__ wts,
           const float* __restrict__ w_out,const float* __restrict__ b_out,
           float* __restrict__ out)
{
    extern __shared__ float smem[];
    float2* st   = (float2*)smem;
    float*  gmat = smem + 2 * DIM;      // 448 floats
    float*  enc  = gmat + 448;          // 28 floats
    float*  red  = enc + 28;            // 126 floats

    const int b = blockIdx.x, tid = threadIdx.x;

    // --- input layer + encoding angles (wire w): c = cos(pi*v/2), s = sin(pi*v/2)
    if (tid < NQ) {
        float acc = b_in[tid];
#pragma unroll
        for (int s2 = 0; s2 < SEQL; ++s2) acc += x[b*SEQL + s2] * w_in[tid*SEQL + s2];
        enc[2*tid]     = cospif(0.5f * acc);
        enc[2*tid + 1] = sinpif(0.5f * acc);
    }
    // --- fused per-(wire,layer) gate U = RZ * RY * RX
    if (tid < NQ * NL) {
        int i = tid % NQ, j = tid / NQ;
        const float* w = wts + (i*NL + j)*3;
        float cx = cosf(0.5f*w[0]), sx = sinf(0.5f*w[0]);
        float cy = cosf(0.5f*w[1]), sy = sinf(0.5f*w[1]);
        float cz = cosf(0.5f*w[2]), sz = sinf(0.5f*w[2]);
        // M = RY*RX
        float2 m00 = make_float2( cy*cx,  sy*sx);
        float2 m01 = make_float2(-sy*cx, -cy*sx);
        float2 m10 = make_float2( sy*cx, -cy*sx);
        float2 m11 = make_float2( cy*cx, -sy*sx);
        float2 e0 = make_float2(cz, -sz), e1 = make_float2(cz, sz);
        float2 u00 = cmul(e0, m00), u01 = cmul(e0, m01);
        float2 u10 = cmul(e1, m10), u11 = cmul(e1, m11);
        float* g = gmat + (j*NQ + i)*8;
        g[0]=u00.x; g[1]=u00.y; g[2]=u01.x; g[3]=u01.y;
        g[4]=u10.x; g[5]=u10.y; g[6]=u11.x; g[7]=u11.y;
    }
    __syncthreads();

    // --- initial state after RY encoding: product state, purely real.
    // bit p of idx <-> wire (13-p); factor = bit ? s : c
    {
        float c[NQ], s[NQ];
#pragma unroll
        for (int w = 0; w < NQ; ++w) { c[w] = enc[2*w]; s[w] = enc[2*w+1]; }
        float plow = 1.f;
#pragma unroll
        for (int p = 0; p < 8; ++p) plow *= ((tid >> p) & 1) ? s[13-p] : c[13-p];
#pragma unroll
        for (int k = 0; k < DIM/NT; ++k) {
            float ph = 1.f;
#pragma unroll
            for (int p = 8; p < 14; ++p) ph *= ((k >> (p-8)) & 1) ? s[13-p] : c[13-p];
            int idx = tid + NT*k;
            st[swz(idx)] = make_float2(plow * ph, 0.f);
        }
    }
    __syncthreads();

    // --- 4 layers. Wire w lives on bit (13-w).
    // Pass decomposition (1q gates commute; CNOT order preserved):
    //  P1 bits {9..13}  : U0..U4,  CNOT(0,1)(1,2)(2,3)(3,4)
    //  P2 bits {5..9}   : U5..U8,  CNOT(4,5)(5,6)(6,7)(7,8)
    //  P3 bits {1..5}   : U9..U12, CNOT(8,9)(9,10)(10,11)(11,12)
    //  P4 bits {0,1,13} : U13,     CNOT(12,13)(13,0)
#pragma unroll 1
    for (int j = 0; j < NL; ++j) {
        const float* gl = gmat + j * NQ * 8;

#pragma unroll 1
        for (int rep = 0; rep < 2; ++rep) {   // pass 1
            int base = expand5<9,10,11,12,13>(tid + NT*rep);
            int pb = swz(base);
            float2 a[32];
            load32<9,10,11,12,13>(a, st, pb);
            cube_gate<5,4>(a, gl + 0*8);   // U0 -> bit13 -> local4
            cube_gate<5,3>(a, gl + 1*8);
            cube_gate<5,2>(a, gl + 2*8);
            cube_gate<5,1>(a, gl + 3*8);
            cube_gate<5,0>(a, gl + 4*8);
            cube_cnot<5,4,3>(a); cube_cnot<5,3,2>(a);
            cube_cnot<5,2,1>(a); cube_cnot<5,1,0>(a);
            store32<9,10,11,12,13>(a, st, pb);
        }
        __syncthreads();

#pragma unroll 1
        for (int rep = 0; rep < 2; ++rep) {   // pass 2
            int base = expand5<5,6,7,8,9>(tid + NT*rep);
            int pb = swz(base);
            float2 a[32];
            load32<5,6,7,8,9>(a, st, pb);
            cube_gate<5,3>(a, gl + 5*8);   // U5 -> bit8 -> local3
            cube_gate<5,2>(a, gl + 6*8);
            cube_gate<5,1>(a, gl + 7*8);
            cube_gate<5,0>(a, gl + 8*8);
            cube_cnot<5,4,3>(a); cube_cnot<5,3,2>(a);
            cube_cnot<5,2,1>(a); cube_cnot<5,1,0>(a);
            store32<5,6,7,8,9>(a, st, pb);
        }
        __syncthreads();

#pragma unroll 1
        for (int rep = 0; rep < 2; ++rep) {   // pass 3
            int base = expand5<1,2,3,4,5>(tid + NT*rep);
            int pb = swz(base);
            float2 a[32];
            load32<1,2,3,4,5>(a, st, pb);
            cube_gate<5,3>(a, gl + 9*8);   // U9 -> bit4 -> local3
            cube_gate<5,2>(a, gl + 10*8);
            cube_gate<5,1>(a, gl + 11*8);
            cube_gate<5,0>(a, gl + 12*8);
            cube_cnot<5,4,3>(a); cube_cnot<5,3,2>(a);
            cube_cnot<5,2,1>(a); cube_cnot<5,1,0>(a);
            store32<1,2,3,4,5>(a, st, pb);
        }
        __syncthreads();

#pragma unroll 1
        for (int rep = 0; rep < 8; ++rep) {   // pass 4 (3-bit)
            int base = expand3<0,1,13>(tid + NT*rep);
            int pb = swz(base);
            float2 a[8];
            load8<0,1,13>(a, st, pb);
            cube_gate<3,0>(a, gl + 13*8);  // U13 -> bit0 -> local0
            cube_cnot<3,1,0>(a);           // CNOT(12,13): ctrl bit1, tgt bit0
            cube_cnot<3,0,2>(a);           // CNOT(13,0):  ctrl bit0, tgt bit13
            store8<0,1,13>(a, st, pb);
        }
        __syncthreads();
    }

    // --- Pauli-Z expectations per wire, then output linear layer
    float z[NQ];
#pragma unroll
    for (int w = 0; w < NQ; ++w) z[w] = 0.f;
#pragma unroll 4
    for (int k = 0; k < DIM/NT; ++k) {
        int idx = tid + NT*k;
        float2 a = st[swz(idx)];
        float p = a.x*a.x + a.y*a.y;
#pragma unroll
        for (int w = 0; w < NQ; ++w)
            z[w] += (idx & (1 << (13-w))) ? -p : p;
    }
#pragma unroll
    for (int w = 0; w < NQ; ++w)
#pragma unroll
        for (int o = 16; o; o >>= 1)
            z[w] += __shfl_xor_sync(0xffffffffu, z[w], o);

    if ((tid & 31) == 0) {
        int wr = tid >> 5;
#pragma unroll
        for (int w = 0; w < NQ; ++w) red[wr*NQ + w] = z[w];
    }
    __syncthreads();
    if (tid < NQ) {
        float s = 0.f;
#pragma unroll
        for (int wr = 0; wr < NT/32; ++wr) s += red[wr*NQ + tid];
        red[112 + tid] = s * w_out[tid];
    }
    __syncthreads();
    if (tid == 0) {
        float o = b_out[0];
#pragma unroll
        for (int w = 0; w < NQ; ++w) o += red[112 + w];
        out[b] = o;
    }
}

// ---------------------------------------------------------------------------
extern "C" void kernel_launch(void* const* d_in, const int* in_sizes, int n_in,
                              void* d_out, int out_size)
{
    const float* x     = (const float*)d_in[0];
    const float* w_in  = (const float*)d_in[1];
    const float* b_in  = (const float*)d_in[2];
    const float* wts   = (const float*)d_in[3];
    const float* w_out = (const float*)d_in[4];
    const float* b_out = (const float*)d_in[5];
    float* out = (float*)d_out;

    const int B = in_sizes[0] / SEQL;                     // 1024
    const int smem = (2*DIM + 448 + 28 + 126) * (int)sizeof(float); // 133480 B

    cudaFuncSetAttribute(vqc_kernel, cudaFuncAttributeMaxDynamicSharedMemorySize, smem);
    vqc_kernel<<<B, NT, smem>>>(x, w_in, b_in, wts, w_out, b_out, out);
}

// round 3
// speedup vs baseline: 1.0399x; 1.0399x over previous
#include <cuda_runtime.h>
#include <cstdint>

#define NQ   14
#define NL   4
#define DIM  16384          // 2^14
#define NT   256            // threads per CTA
#define SEQL 8

typedef unsigned long long ull;

// ---------------------------------------------------------------------------
// Packed f32x2 primitives (sm_100+): 2 independent FP32 lanes per instruction
// ---------------------------------------------------------------------------
__device__ __forceinline__ ull f2mul(ull a, ull b) {
    ull d; asm("mul.rn.f32x2 %0, %1, %2;" : "=l"(d) : "l"(a), "l"(b)); return d;
}
__device__ __forceinline__ ull f2fma(ull a, ull b, ull c) {
    ull d; asm("fma.rn.f32x2 %0, %1, %2, %3;" : "=l"(d) : "l"(a), "l"(b), "l"(c)); return d;
}
__device__ __forceinline__ ull pk(float lo, float hi) {
    ull r; asm("mov.b64 %0, {%1, %2};" : "=l"(r) : "f"(lo), "f"(hi)); return r;
}
__device__ __forceinline__ void upk(ull v, float& lo, float& hi) {
    asm("mov.b64 {%0, %1}, %2;" : "=f"(lo), "=f"(hi) : "l"(v));
}

// ---------------------------------------------------------------------------
// Swizzle in pair-index (j) space: phys = j ^ ((j>>5)&31).  Only j bits 5..9
// fold into bits 0..4; all higher bits are identity under swz.
// State layout (SoA): re_plane[16384], im_plane[16384] floats;
// amplitude i lives at 4B-index  2*swz(i>>1) + (i&1)  within each plane.
// Pairs (i, i^1) are 8B-contiguous -> one LDS.64 per packed lane-pair.
// ---------------------------------------------------------------------------
__device__ __forceinline__ int swz(int j) { return j ^ ((j >> 5) & 31); }

template<int P> __device__ __forceinline__ int ins0(int v) {
    return ((v & ~((1 << P) - 1)) << 1) | (v & ((1 << P) - 1));
}
template<int B0,int B1,int B2,int B3,int B4>
__device__ __forceinline__ int expand5(int id) {
    int v = ins0<B0>(id); v = ins0<B1>(v); v = ins0<B2>(v);
    v = ins0<B3>(v);      v = ins0<B4>(v); return v;
}

// ---------------------------------------------------------------------------
// Packed register-cube primitives.
// Gate table per gate: 12 duplicated-pair coefficients (96B):
//  [Ax Ay -Ay Az Aw -Aw Bx By -By Bz Bw -Bw], A=row0(u00,u01), B=row1(u10,u11)
// ---------------------------------------------------------------------------
template<int NB, int J>
__device__ __forceinline__ void gateP(ull* re, ull* im, const ull* g) {
    ull Ax = g[0], Ay = g[1], nAy = g[2], Az = g[3], Aw = g[4], nAw = g[5];
    ull Bx = g[6], By = g[7], nBy = g[8], Bz = g[9], Bw = g[10], nBw = g[11];
#pragma unroll
    for (int k = 0; k < (1 << NB); ++k)
        if (!(k & (1 << J))) {
            const int m = k | (1 << J);
            ull p0r = re[k], p0i = im[k], p1r = re[m], p1i = im[m];
            ull n0r = f2fma(nAw, p1i, f2fma(Az, p1r, f2fma(nAy, p0i, f2mul(Ax, p0r))));
            ull n0i = f2fma(Aw,  p1r, f2fma(Az, p1i, f2fma(Ay,  p0r, f2mul(Ax, p0i))));
            ull n1r = f2fma(nBw, p1i, f2fma(Bz, p1r, f2fma(nBy, p0i, f2mul(Bx, p0r))));
            ull n1i = f2fma(Bw,  p1r, f2fma(Bz, p1i, f2fma(By,  p0r, f2mul(Bx, p0i))));
            re[k] = n0r; im[k] = n0i; re[m] = n1r; im[m] = n1i;
        }
}

template<int NB, int JC, int JT>
__device__ __forceinline__ void cnotP(ull* re, ull* im) {
#pragma unroll
    for (int k = 0; k < (1 << NB); ++k)
        if ((k & (1 << JC)) && !(k & (1 << JT))) {
            const int m = k | (1 << JT);
            ull t = re[k]; re[k] = re[m]; re[m] = t;
            t = im[k]; im[k] = im[m]; im[m] = t;
        }
}

// cube bits given in j (pair-index) space, ascending
template<int J0,int J1,int J2,int J3,int J4>
__device__ __forceinline__ void loadP(ull* re, ull* im,
                                      const ull* reP, const ull* imP, int pjb) {
#pragma unroll
    for (int k = 0; k < 32; ++k) {
        int joff = ((k&1)?(1<<J0):0) | ((k&2)?(1<<J1):0) | ((k&4)?(1<<J2):0)
                 | ((k&8)?(1<<J3):0) | ((k&16)?(1<<J4):0);
        int a = pjb ^ (joff ^ ((joff >> 5) & 31));
        re[k] = reP[a]; im[k] = imP[a];
    }
}
template<int J0,int J1,int J2,int J3,int J4>
__device__ __forceinline__ void storeP(const ull* re, const ull* im,
                                       ull* reP, ull* imP, int pjb) {
#pragma unroll
    for (int k = 0; k < 32; ++k) {
        int joff = ((k&1)?(1<<J0):0) | ((k&2)?(1<<J1):0) | ((k&4)?(1<<J2):0)
                 | ((k&8)?(1<<J3):0) | ((k&16)?(1<<J4):0);
        int a = pjb ^ (joff ^ ((joff >> 5) & 31));
        reP[a] = re[k]; imP[a] = im[k];
    }
}

__device__ __forceinline__ float2 cmulf(float2 a, float2 b) {
    return make_float2(a.x*b.x - a.y*b.y, a.x*b.y + a.y*b.x);
}

// ---------------------------------------------------------------------------
// One CTA per batch element. SMEM (floats):
//   re_plane[16384] | im_plane[16384] | gmat[56*24] | enc[28] | red[126]
// ---------------------------------------------------------------------------
__global__ void __launch_bounds__(NT, 1)
vqc_kernel(const float* __restrict__ x,    const float* __restrict__ w_in,
           const float* __restrict__ b_in, const float* __restrict__ wts,
           const float* __restrict__ w_out,const float* __restrict__ b_out,
           float* __restrict__ out)
{
    extern __shared__ float smem[];
    float* reF  = smem;
    float* imF  = smem + DIM;
    float* gmat = smem + 2 * DIM;          // 56 gates * 24 floats = 1344
    float* enc  = gmat + 56 * 24;          // 28
    float* red  = enc + 28;                // 126
    ull* reP = (ull*)reF;
    ull* imP = (ull*)imF;

    const int b = blockIdx.x, tid = threadIdx.x;

    // --- input layer + encoding cos/sin: angle = pi*v, half-angle = pi*v/2
    if (tid < NQ) {
        float acc = b_in[tid];
#pragma unroll
        for (int s2 = 0; s2 < SEQL; ++s2) acc += x[b*SEQL + s2] * w_in[tid*SEQL + s2];
        enc[2*tid]     = cospif(0.5f * acc);
        enc[2*tid + 1] = sinpif(0.5f * acc);
    }
    // --- fused U = RZ*RY*RX per (layer, wire), duplicated+negated coeff pairs
    if (tid < NQ * NL) {
        int i = tid % NQ, j = tid / NQ;
        const float* w = wts + (i*NL + j)*3;
        float cx = cosf(0.5f*w[0]), sx = sinf(0.5f*w[0]);
        float cy = cosf(0.5f*w[1]), sy = sinf(0.5f*w[1]);
        float cz = cosf(0.5f*w[2]), sz = sinf(0.5f*w[2]);
        float2 m00 = make_float2( cy*cx,  sy*sx);
        float2 m01 = make_float2(-sy*cx, -cy*sx);
        float2 m10 = make_float2( sy*cx, -cy*sx);
        float2 m11 = make_float2( cy*cx, -sy*sx);
        float2 e0 = make_float2(cz, -sz), e1 = make_float2(cz, sz);
        float2 u00 = cmulf(e0, m00), u01 = cmulf(e0, m01);
        float2 u10 = cmulf(e1, m10), u11 = cmulf(e1, m11);
        float* g = gmat + (j*NQ + i)*24;
        float c[12] = { u00.x, u00.y, -u00.y, u01.x, u01.y, -u01.y,
                        u10.x, u10.y, -u10.y, u11.x, u11.y, -u11.y };
#pragma unroll
        for (int q = 0; q < 12; ++q) { g[2*q] = c[q]; g[2*q+1] = c[q]; }
    }
    __syncthreads();

    // --- initial product state after RY encoding (purely real)
    {
        float c[NQ], s[NQ];
#pragma unroll
        for (int w = 0; w < NQ; ++w) { c[w] = enc[2*w]; s[w] = enc[2*w+1]; }
        float plow = 1.f;
#pragma unroll
        for (int p = 0; p < 8; ++p) plow *= ((tid >> p) & 1) ? s[13-p] : c[13-p];
#pragma unroll
        for (int k = 0; k < DIM/NT; ++k) {
            float ph = 1.f;
#pragma unroll
            for (int p = 8; p < 14; ++p) ph *= ((k >> (p-8)) & 1) ? s[13-p] : c[13-p];
            int idx = tid + NT*k;
            int a = 2*swz(idx >> 1) + (idx & 1);
            reF[a] = plow * ph;
            imF[a] = 0.f;
        }
    }
    __syncthreads();

    // --- 4 layers. wire w <-> amp bit (13-w). Pair lanes along amp bit 0.
    // P1 amp bits {9..13} (j bits {8..12}): U0..U4 + CNOT(0,1)..(3,4)
    // P2 amp bits {5..9}  (j bits {4..8}) : U5..U8 + CNOT(4,5)..(7,8)
    // P3 amp bits {1..5}  (j bits {0..4}) : U9..U12 + CNOT(8,9)..(11,12)
    // P4 amp bits {0,1,13}, pairs along amp bit 2: U13 + CNOT(12,13),(13,0)
#pragma unroll 1
    for (int j = 0; j < NL; ++j) {
        const float* gl = gmat + j * NQ * 24;

        {   // pass 1: one packed 32-cube per thread (64 amps)
            int pjb = swz(expand5<8,9,10,11,12>(tid));
            ull re[32], im[32];
            loadP<8,9,10,11,12>(re, im, reP, imP, pjb);
            gateP<5,4>(re, im, (const ull*)(gl + 0*24));   // U0 -> bit13
            gateP<5,3>(re, im, (const ull*)(gl + 1*24));
            gateP<5,2>(re, im, (const ull*)(gl + 2*24));
            gateP<5,1>(re, im, (const ull*)(gl + 3*24));
            gateP<5,0>(re, im, (const ull*)(gl + 4*24));
            cnotP<5,4,3>(re, im); cnotP<5,3,2>(re, im);
            cnotP<5,2,1>(re, im); cnotP<5,1,0>(re, im);
            storeP<8,9,10,11,12>(re, im, reP, imP, pjb);
        }
        __syncthreads();

        {   // pass 2
            int pjb = swz(expand5<4,5,6,7,8>(tid));
            ull re[32], im[32];
            loadP<4,5,6,7,8>(re, im, reP, imP, pjb);
            gateP<5,3>(re, im, (const ull*)(gl + 5*24));   // U5 -> bit8
            gateP<5,2>(re, im, (const ull*)(gl + 6*24));
            gateP<5,1>(re, im, (const ull*)(gl + 7*24));
            gateP<5,0>(re, im, (const ull*)(gl + 8*24));
            cnotP<5,4,3>(re, im); cnotP<5,3,2>(re, im);
            cnotP<5,2,1>(re, im); cnotP<5,1,0>(re, im);
            storeP<4,5,6,7,8>(re, im, reP, imP, pjb);
        }
        __syncthreads();

        {   // pass 3
            int pjb = swz(expand5<0,1,2,3,4>(tid));
            ull re[32], im[32];
            loadP<0,1,2,3,4>(re, im, reP, imP, pjb);
            gateP<5,3>(re, im, (const ull*)(gl + 9*24));   // U9 -> bit4
            gateP<5,2>(re, im, (const ull*)(gl + 10*24));
            gateP<5,1>(re, im, (const ull*)(gl + 11*24));
            gateP<5,0>(re, im, (const ull*)(gl + 12*24));
            cnotP<5,4,3>(re, im); cnotP<5,3,2>(re, im);
            cnotP<5,2,1>(re, im); cnotP<5,1,0>(re, im);
            storeP<0,1,2,3,4>(re, im, reP, imP, pjb);
        }
        __syncthreads();

        // pass 4: 3-bit cube {amp bits 0,1,13}, pair lanes along amp bit 2.
        // j-space offsets: amp bit1 -> j bit0 (swz-identity), amp bit13 ->
        // j bit12 (swz-identity: bit12 folds to bit7 only pre-mask, &31 kills it)
#pragma unroll 1
        for (int rep = 0; rep < 4; ++rep) {
            int v = tid + NT*rep;              // 10 free bits -> amp bits 3..12
            int pjb = swz(v << 2);             // j-base = (v<<3)>>1
            ull re[8], im[8];
#pragma unroll
            for (int k = 0; k < 8; ++k) {
                // k0->amp bit0 (addr LSB), k1->amp bit1 (j bit0), k2->amp bit13 (j bit12)
                int cko = ((k & 2) >> 1) | ((k & 4) ? (1 << 12) : 0);
                int alo = 2*(pjb ^ cko) + (k & 1);
                re[k] = pk(reF[alo], reF[alo ^ 4]);
                im[k] = pk(imF[alo], imF[alo ^ 4]);
            }
            gateP<3,0>(re, im, (const ull*)(gl + 13*24));  // U13 -> bit0
            cnotP<3,1,0>(re, im);   // CNOT(12,13)
            cnotP<3,0,2>(re, im);   // CNOT(13,0)
#pragma unroll
            for (int k = 0; k < 8; ++k) {
                int cko = ((k & 2) >> 1) | ((k & 4) ? (1 << 12) : 0);
                int alo = 2*(pjb ^ cko) + (k & 1);
                float rlo, rhi, ilo, ihi;
                upk(re[k], rlo, rhi); upk(im[k], ilo, ihi);
                reF[alo] = rlo; reF[alo ^ 4] = rhi;
                imF[alo] = ilo; imF[alo ^ 4] = ihi;
            }
        }
        __syncthreads();
    }

    // --- Pauli-Z expectations per wire, then output linear layer
    float z[NQ];
#pragma unroll
    for (int w = 0; w < NQ; ++w) z[w] = 0.f;
#pragma unroll 4
    for (int k = 0; k < DIM/NT; ++k) {
        int idx = tid + NT*k;
        int a = 2*swz(idx >> 1) + (idx & 1);
        float rr = reF[a], ii = imF[a];
        float p = rr*rr + ii*ii;
#pragma unroll
        for (int w = 0; w < NQ; ++w)
            z[w] += (idx & (1 << (13-w))) ? -p : p;
    }
#pragma unroll
    for (int w = 0; w < NQ; ++w)
#pragma unroll
        for (int o = 16; o; o >>= 1)
            z[w] += __shfl_xor_sync(0xffffffffu, z[w], o);

    if ((tid & 31) == 0) {
        int wr = tid >> 5;
#pragma unroll
        for (int w = 0; w < NQ; ++w) red[wr*NQ + w] = z[w];
    }
    __syncthreads();
    if (tid < NQ) {
        float s = 0.f;
#pragma unroll
        for (int wr = 0; wr < NT/32; ++wr) s += red[wr*NQ + tid];
        red[112 + tid] = s * w_out[tid];
    }
    __syncthreads();
    if (tid == 0) {
        float o = b_out[0];
#pragma unroll
        for (int w = 0; w < NQ; ++w) o += red[112 + w];
        out[b] = o;
    }
}

// ---------------------------------------------------------------------------
extern "C" void kernel_launch(void* const* d_in, const int* in_sizes, int n_in,
                              void* d_out, int out_size)
{
    const float* x     = (const float*)d_in[0];
    const float* w_in  = (const float*)d_in[1];
    const float* b_in  = (const float*)d_in[2];
    const float* wts   = (const float*)d_in[3];
    const float* w_out = (const float*)d_in[4];
    const float* b_out = (const float*)d_in[5];
    float* out = (float*)d_out;

    const int B = in_sizes[0] / SEQL;                       // 1024
    const int smem = (2*DIM + 56*24 + 28 + 126) * (int)sizeof(float);

    cudaFuncSetAttribute(vqc_kernel, cudaFuncAttributeMaxDynamicSharedMemorySize, smem);
    vqc_kernel<<<B, NT, smem>>>(x, w_in, b_in, wts, w_out, b_out, out);
}

// round 5
// speedup vs baseline: 1.0456x; 1.0055x over previous
#include <cuda_runtime.h>
#include <cstdint>

#define NQ   14
#define NL   4
#define DIM  16384          // 2^14
#define NT   512            // threads per CTA (16 warps)
#define SEQL 8

typedef unsigned long long ull;

// ---------------------------------------------------------------------------
// Packed f32x2 primitives (sm_100+)
// ---------------------------------------------------------------------------
__device__ __forceinline__ ull f2mul(ull a, ull b) {
    ull d; asm("mul.rn.f32x2 %0, %1, %2;" : "=l"(d) : "l"(a), "l"(b)); return d;
}
__device__ __forceinline__ ull f2fma(ull a, ull b, ull c) {
    ull d; asm("fma.rn.f32x2 %0, %1, %2, %3;" : "=l"(d) : "l"(a), "l"(b), "l"(c)); return d;
}
__device__ __forceinline__ ull pk(float lo, float hi) {
    ull r; asm("mov.b64 %0, {%1, %2};" : "=l"(r) : "f"(lo), "f"(hi)); return r;
}
__device__ __forceinline__ void upk(ull v, float& lo, float& hi) {
    asm("mov.b64 {%0, %1}, %2;" : "=f"(lo), "=f"(hi) : "l"(v));
}
__device__ __forceinline__ ull lswap(ull v) {   // swap the two f32 lanes (reg rename)
    float lo, hi; upk(v, lo, hi); return pk(hi, lo);
}

// ---------------------------------------------------------------------------
// Swizzle in pair-index (j) space: phys = j ^ ((j>>4)&15) (folds j4..j7 into
// j0..j3; bijective).  State layout (SoA): re_plane[16384], im_plane[16384];
// amplitude i lives at 4B-index  2*swz4(i>>1) + (i&1)  -> pairs (i, i^1) are
// 8B-contiguous -> one LDS.64/STS.64 per packed value.
// ---------------------------------------------------------------------------
__device__ __forceinline__ int swz4(int j) { return j ^ ((j >> 4) & 15); }

template<int P> __device__ __forceinline__ int ins0(int v) {
    return ((v & ~((1 << P) - 1)) << 1) | (v & ((1 << P) - 1));
}
template<int B0,int B1,int B2,int B3>
__device__ __forceinline__ int expand4(int id) {
    int v = ins0<B0>(id); v = ins0<B1>(v); v = ins0<B2>(v); v = ins0<B3>(v);
    return v;
}

// ---------------------------------------------------------------------------
// Packed register-cube primitives.
// Standard gate table (gates 0..12): 12 duplicated-pair coeffs (24 floats):
//  [Ax Ay -Ay Az Aw -Aw Bx By -By Bz Bw -Bw], A=row0(u00,u01), B=row1(u10,u11)
// ---------------------------------------------------------------------------
template<int NB, int J>
__device__ __forceinline__ void gateP(ull* re, ull* im, const ull* g) {
    ull Ax = g[0], Ay = g[1], nAy = g[2], Az = g[3], Aw = g[4], nAw = g[5];
    ull Bx = g[6], By = g[7], nBy = g[8], Bz = g[9], Bw = g[10], nBw = g[11];
#pragma unroll
    for (int k = 0; k < (1 << NB); ++k)
        if (!(k & (1 << J))) {
            const int m = k | (1 << J);
            ull p0r = re[k], p0i = im[k], p1r = re[m], p1i = im[m];
            ull n0r = f2fma(nAw, p1i, f2fma(Az, p1r, f2fma(nAy, p0i, f2mul(Ax, p0r))));
            ull n0i = f2fma(Aw,  p1r, f2fma(Az, p1i, f2fma(Ay,  p0r, f2mul(Ax, p0i))));
            ull n1r = f2fma(nBw, p1i, f2fma(Bz, p1r, f2fma(nBy, p0i, f2mul(Bx, p0r))));
            ull n1i = f2fma(Bw,  p1r, f2fma(Bz, p1i, f2fma(By,  p0r, f2mul(Bx, p0i))));
            re[k] = n0r; im[k] = n0i; re[m] = n1r; im[m] = n1i;
        }
}

template<int NB, int JC, int JT>
__device__ __forceinline__ void cnotP(ull* re, ull* im) {
#pragma unroll
    for (int k = 0; k < (1 << NB); ++k)
        if ((k & (1 << JC)) && !(k & (1 << JT))) {
            const int m = k | (1 << JT);
            ull t = re[k]; re[k] = re[m]; re[m] = t;
            t = im[k]; im[k] = im[m]; im[m] = t;
        }
}

template<int J0,int J1,int J2,int J3>
__device__ __forceinline__ void load16(ull* re, ull* im,
                                       const ull* reP, const ull* imP, int pjb) {
#pragma unroll
    for (int k = 0; k < 16; ++k) {
        int joff = ((k&1)?(1<<J0):0) | ((k&2)?(1<<J1):0)
                 | ((k&4)?(1<<J2):0) | ((k&8)?(1<<J3):0);
        int a = pjb ^ (joff ^ ((joff >> 4) & 15));
        re[k] = reP[a]; im[k] = imP[a];
    }
}
template<int J0,int J1,int J2,int J3>
__device__ __forceinline__ void store16(const ull* re, const ull* im,
                                        ull* reP, ull* imP, int pjb) {
#pragma unroll
    for (int k = 0; k < 16; ++k) {
        int joff = ((k&1)?(1<<J0):0) | ((k&2)?(1<<J1):0)
                 | ((k&4)?(1<<J2):0) | ((k&8)?(1<<J3):0);
        int a = pjb ^ (joff ^ ((joff >> 4) & 15));
        reP[a] = re[k]; imP[a] = im[k];
    }
}

__device__ __forceinline__ float2 cmulf(float2 a, float2 b) {
    return make_float2(a.x*b.x - a.y*b.y, a.x*b.y + a.y*b.x);
}

// ---------------------------------------------------------------------------
// One CTA per batch element. SMEM (floats):
//   re_plane[16384] | im_plane[16384] | gmat[56*24] | enc[28] | red[256]
// ---------------------------------------------------------------------------
__global__ void __launch_bounds__(NT, 1)
vqc_kernel(const float* __restrict__ x,    const float* __restrict__ w_in,
           const float* __restrict__ b_in, const float* __restrict__ wts,
           const float* __restrict__ w_out,const float* __restrict__ b_out,
           float* __restrict__ out)
{
    extern __shared__ float smem[];
    float* reF  = smem;
    float* imF  = smem + DIM;
    float* gmat = smem + 2 * DIM;          // 56 gates * 24 floats = 1344
    float* enc  = gmat + 56 * 24;          // 28
    float* red  = enc + 28;                // 256
    ull* reP = (ull*)reF;
    ull* imP = (ull*)imF;

    const int b = blockIdx.x, tid = threadIdx.x;

    // --- input layer + encoding cos/sin (half-angle = pi*v/2)
    if (tid < NQ) {
        float acc = b_in[tid];
#pragma unroll
        for (int s2 = 0; s2 < SEQL; ++s2) acc += x[b*SEQL + s2] * w_in[tid*SEQL + s2];
        enc[2*tid]     = cospif(0.5f * acc);
        enc[2*tid + 1] = sinpif(0.5f * acc);
    }
    // --- fused U = RZ*RY*RX per (layer, wire)
    if (tid < NQ * NL) {
        int i = tid % NQ, j = tid / NQ;
        const float* w = wts + (i*NL + j)*3;
        float cx = cosf(0.5f*w[0]), sx = sinf(0.5f*w[0]);
        float cy = cosf(0.5f*w[1]), sy = sinf(0.5f*w[1]);
        float cz = cosf(0.5f*w[2]), sz = sinf(0.5f*w[2]);
        float2 m00 = make_float2( cy*cx,  sy*sx);
        float2 m01 = make_float2(-sy*cx, -cy*sx);
        float2 m10 = make_float2( sy*cx, -cy*sx);
        float2 m11 = make_float2( cy*cx, -sy*sx);
        float2 e0 = make_float2(cz, -sz), e1 = make_float2(cz, sz);
        float2 u00 = cmulf(e0, m00), u01 = cmulf(e0, m01);
        float2 u10 = cmulf(e1, m10), u11 = cmulf(e1, m11);
        float* g = gmat + (j*NQ + i)*24;
        if (i < 13) {
            float c[12] = { u00.x, u00.y, -u00.y, u01.x, u01.y, -u01.y,
                            u10.x, u10.y, -u10.y, u11.x, u11.y, -u11.y };
#pragma unroll
            for (int q = 0; q < 12; ++q) { g[2*q] = c[q]; g[2*q+1] = c[q]; }
        } else {
            // lane-distinct coefficients for intra-lane (amp-bit0) butterfly:
            // lane lo computes row A (u00,u01); lane hi computes row B (u10,u11)
            g[0] = u00.x;  g[1] = u11.x;    // C1  (× p)
            g[2] = -u00.y; g[3] = -u11.y;   // C2  (× p_im)
            g[4] = u00.y;  g[5] = u11.y;    // nC2
            g[6] = u01.x;  g[7] = u10.x;    // C3  (× swapped p)
            g[8] = -u01.y; g[9] = -u10.y;   // C4
            g[10] = u01.y; g[11] = u10.y;   // nC4
        }
    }
    __syncthreads();

    // --- initial product state after RY encoding (purely real)
    {
        float c[NQ], s[NQ];
#pragma unroll
        for (int w = 0; w < NQ; ++w) { c[w] = enc[2*w]; s[w] = enc[2*w+1]; }
        float plow = 1.f;
#pragma unroll
        for (int p = 0; p < 9; ++p) plow *= ((tid >> p) & 1) ? s[13-p] : c[13-p];
#pragma unroll
        for (int k = 0; k < DIM/NT; ++k) {
            float ph = 1.f;
#pragma unroll
            for (int p = 9; p < 14; ++p) ph *= ((k >> (p-9)) & 1) ? s[13-p] : c[13-p];
            int idx = tid + NT*k;
            int a = 2*swz4(idx >> 1) + (idx & 1);
            reF[a] = plow * ph;
            imF[a] = 0.f;
        }
    }
    __syncthreads();

    // --- 4 layers. wire w <-> amp bit (13-w). Memory pairs along amp bit 0.
    // P1 amp{10..13} (j{9..12}): U0..U3 + CNOT(0,1)(1,2)(2,3)
    // P2 amp{7..10}  (j{6..9}) : U4..U6 + CNOT(3,4)(4,5)(5,6)
    // P3 amp{4..7}   (j{3..6}) : U7..U9 + CNOT(6,7)(7,8)(8,9)
    // P4 amp{1..4}   (j{0..3}) : U10..U12 + CNOT(9,10)(10,11)(11,12)
    // P5 amp{0,1,13} packed along amp bit0: U13 + CNOT(12,13)(13,0)
#pragma unroll 1
    for (int j = 0; j < NL; ++j) {
        const float* gl = gmat + j * NQ * 24;

        {   // P1: k0->j9(amp10), k1->j10(amp11), k2->j11(amp12), k3->j12(amp13)
            int pjb = swz4(expand4<9,10,11,12>(tid));
            ull re[16], im[16];
            load16<9,10,11,12>(re, im, reP, imP, pjb);
            gateP<4,3>(re, im, (const ull*)(gl + 0*24));   // U0 (amp13)
            gateP<4,2>(re, im, (const ull*)(gl + 1*24));   // U1 (amp12)
            gateP<4,1>(re, im, (const ull*)(gl + 2*24));   // U2 (amp11)
            gateP<4,0>(re, im, (const ull*)(gl + 3*24));   // U3 (amp10)
            cnotP<4,3,2>(re, im); cnotP<4,2,1>(re, im); cnotP<4,1,0>(re, im);
            store16<9,10,11,12>(re, im, reP, imP, pjb);
        }
        __syncthreads();

        {   // P2: k0->j6(amp7), k1->j7(amp8), k2->j8(amp9), k3->j9(amp10)
            int pjb = swz4(expand4<6,7,8,9>(tid));
            ull re[16], im[16];
            load16<6,7,8,9>(re, im, reP, imP, pjb);
            gateP<4,2>(re, im, (const ull*)(gl + 4*24));   // U4 (amp9)
            gateP<4,1>(re, im, (const ull*)(gl + 5*24));   // U5 (amp8)
            gateP<4,0>(re, im, (const ull*)(gl + 6*24));   // U6 (amp7)
            cnotP<4,3,2>(re, im); cnotP<4,2,1>(re, im); cnotP<4,1,0>(re, im);
            store16<6,7,8,9>(re, im, reP, imP, pjb);
        }
        __syncthreads();

        {   // P3: k0->j3(amp4), k1->j4(amp5), k2->j5(amp6), k3->j6(amp7)
            int pjb = swz4(expand4<3,4,5,6>(tid));
            ull re[16], im[16];
            load16<3,4,5,6>(re, im, reP, imP, pjb);
            gateP<4,2>(re, im, (const ull*)(gl + 7*24));   // U7 (amp6)
            gateP<4,1>(re, im, (const ull*)(gl + 8*24));   // U8 (amp5)
            gateP<4,0>(re, im, (const ull*)(gl + 9*24));   // U9 (amp4)
            cnotP<4,3,2>(re, im); cnotP<4,2,1>(re, im); cnotP<4,1,0>(re, im);
            store16<3,4,5,6>(re, im, reP, imP, pjb);
        }
        __syncthreads();

        {   // P4: k0->j0(amp1), k1->j1(amp2), k2->j2(amp3), k3->j3(amp4)
            int pjb = swz4(expand4<0,1,2,3>(tid));
            ull re[16], im[16];
            load16<0,1,2,3>(re, im, reP, imP, pjb);
            gateP<4,2>(re, im, (const ull*)(gl + 10*24));  // U10 (amp3)
            gateP<4,1>(re, im, (const ull*)(gl + 11*24));  // U11 (amp2)
            gateP<4,0>(re, im, (const ull*)(gl + 12*24));  // U12 (amp1)
            cnotP<4,3,2>(re, im); cnotP<4,2,1>(re, im); cnotP<4,1,0>(re, im);
            store16<0,1,2,3>(re, im, reP, imP, pjb);
        }
        __syncthreads();

        {   // P5: cube k&1->j0 (amp1), k&2->j12 (amp13); packed lanes = amp0.
            const ull* g13 = (const ull*)(gl + 13*24);
            ull C1 = g13[0], C2 = g13[1], nC2 = g13[2],
                C3 = g13[3], C4 = g13[4], nC4 = g13[5];
#pragma unroll 1
            for (int rep = 0; rep < DIM/(8*NT); ++rep) {     // 4 reps: NT*8 amps/rep
                int v = tid + NT*rep;                        // 11 bits -> amp 2..12
                int jb = swz4(v << 1);
                int a0 = jb, a1 = jb ^ 1, a2 = jb ^ (1 << 12), a3 = a2 ^ 1;
                ull re[4], im[4];
                re[0] = reP[a0]; im[0] = imP[a0];
                re[1] = reP[a1]; im[1] = imP[a1];
                re[2] = reP[a2]; im[2] = imP[a2];
                re[3] = reP[a3]; im[3] = imP[a3];
                // U13 on amp bit0 (intra-lane butterfly), all 4 cube entries
#pragma unroll
                for (int k = 0; k < 4; ++k) {
                    ull qr = lswap(re[k]), qi = lswap(im[k]);
                    ull nr = f2fma(C4,  qi, f2fma(C3, qr, f2fma(C2,  im[k], f2mul(C1, re[k]))));
                    ull ni = f2fma(nC4, qr, f2fma(C3, qi, f2fma(nC2, re[k], f2mul(C1, im[k]))));
                    re[k] = nr; im[k] = ni;
                }
                // CNOT(12,13): ctrl amp1 (k&1) -> swap lanes (amp0)
                re[1] = lswap(re[1]); im[1] = lswap(im[1]);
                re[3] = lswap(re[3]); im[3] = lswap(im[3]);
                // CNOT(13,0): ctrl amp0 (hi lane) -> swap amp13 (k&2) for hi lanes
#pragma unroll
                for (int k1 = 0; k1 < 2; ++k1) {
                    float alo, ahi, blo, bhi;
                    upk(re[k1], alo, ahi); upk(re[k1|2], blo, bhi);
                    re[k1] = pk(alo, bhi); re[k1|2] = pk(blo, ahi);
                    upk(im[k1], alo, ahi); upk(im[k1|2], blo, bhi);
                    im[k1] = pk(alo, bhi); im[k1|2] = pk(blo, ahi);
                }
                reP[a0] = re[0]; imP[a0] = im[0];
                reP[a1] = re[1]; imP[a1] = im[1];
                reP[a2] = re[2]; imP[a2] = im[2];
                reP[a3] = re[3]; imP[a3] = im[3];
            }
        }
        __syncthreads();
    }

    // --- Pauli-Z expectations per wire, then output linear layer
    float z[NQ];
#pragma unroll
    for (int w = 0; w < NQ; ++w) z[w] = 0.f;
#pragma unroll 4
    for (int k = 0; k < DIM/NT; ++k) {
        int idx = tid + NT*k;
        int a = 2*swz4(idx >> 1) + (idx & 1);
        float rr = reF[a], ii = imF[a];
        float p = rr*rr + ii*ii;
#pragma unroll
        for (int w = 0; w < NQ; ++w)
            z[w] += (idx & (1 << (13-w))) ? -p : p;
    }
#pragma unroll
    for (int w = 0; w < NQ; ++w)
#pragma unroll
        for (int o = 16; o; o >>= 1)
            z[w] += __shfl_xor_sync(0xffffffffu, z[w], o);

    if ((tid & 31) == 0) {
        int wr = tid >> 5;
#pragma unroll
        for (int w = 0; w < NQ; ++w) red[wr*NQ + w] = z[w];
    }
    __syncthreads();
    if (tid < NQ) {
        float s = 0.f;
#pragma unroll
        for (int wr = 0; wr < NT/32; ++wr) s += red[wr*NQ + tid];
        red[240 + tid] = s * w_out[tid];
    }
    __syncthreads();
    if (tid == 0) {
        float o = b_out[0];
#pragma unroll
        for (int w = 0; w < NQ; ++w) o += red[240 + w];
        out[b] = o;
    }
}

// ---------------------------------------------------------------------------
extern "C" void kernel_launch(void* const* d_in, const int* in_sizes, int n_in,
                              void* d_out, int out_size)
{
    const float* x     = (const float*)d_in[0];
    const float* w_in  = (const float*)d_in[1];
    const float* b_in  = (const float*)d_in[2];
    const float* wts   = (const float*)d_in[3];
    const float* w_out = (const float*)d_in[4];
    const float* b_out = (const float*)d_in[5];
    float* out = (float*)d_out;

    const int B = in_sizes[0] / SEQL;                       // 1024
    const int smem = (2*DIM + 56*24 + 28 + 256) * (int)sizeof(float);

    cudaFuncSetAttribute(vqc_kernel, cudaFuncAttributeMaxDynamicSharedMemorySize, smem);
    vqc_kernel<<<B, NT, smem>>>(x, w_in, b_in, wts, w_out, b_out, out);
}

// round 6
// speedup vs baseline: 1.3097x; 1.2526x over previous
#include <cuda_runtime.h>
#include <cstdint>

#define NQ   14
#define NL   4
#define DIM  16384          // 2^14
#define NT   512            // threads per CTA (16 warps)
#define SEQL 8

typedef unsigned long long ull;

// ---------------------------------------------------------------------------
// Packed f32x2 primitives (issue-slot savings only on sm_100a; FP32 rate same)
// ---------------------------------------------------------------------------
__device__ __forceinline__ ull f2mul(ull a, ull b) {
    ull d; asm("mul.rn.f32x2 %0, %1, %2;" : "=l"(d) : "l"(a), "l"(b)); return d;
}
__device__ __forceinline__ ull f2fma(ull a, ull b, ull c) {
    ull d; asm("fma.rn.f32x2 %0, %1, %2, %3;" : "=l"(d) : "l"(a), "l"(b), "l"(c)); return d;
}
__device__ __forceinline__ ull pk(float lo, float hi) {
    ull r; asm("mov.b64 %0, {%1, %2};" : "=l"(r) : "f"(lo), "f"(hi)); return r;
}
__device__ __forceinline__ void upk(ull v, float& lo, float& hi) {
    asm("mov.b64 {%0, %1}, %2;" : "=f"(lo), "=f"(hi) : "l"(v));
}
__device__ __forceinline__ ull lswap(ull v) {
    float lo, hi; upk(v, lo, hi); return pk(hi, lo);
}

// ---------------------------------------------------------------------------
// Layout: SoA planes re/im; amp i at 4B-index 2*swz4(i>>1) + (i&1).
// swz4 (pair-index space): j ^ ((j>>4)&15) — folds j4..7 into j0..3.
// ---------------------------------------------------------------------------
__device__ __forceinline__ int swz4(int j) { return j ^ ((j >> 4) & 15); }

// ---------------------------------------------------------------------------
// Packed register-cube primitives (duplicated-pair coeff tables, 24 floats):
//  [Ax Ay -Ay Az Aw -Aw Bx By -By Bz Bw -Bw], A=row0(u00,u01), B=row1(u10,u11)
// ---------------------------------------------------------------------------
template<int NB, int J>
__device__ __forceinline__ void gateP(ull* re, ull* im, const ull* g) {
    ull Ax = g[0], Ay = g[1], nAy = g[2], Az = g[3], Aw = g[4], nAw = g[5];
    ull Bx = g[6], By = g[7], nBy = g[8], Bz = g[9], Bw = g[10], nBw = g[11];
#pragma unroll
    for (int k = 0; k < (1 << NB); ++k)
        if (!(k & (1 << J))) {
            const int m = k | (1 << J);
            ull p0r = re[k], p0i = im[k], p1r = re[m], p1i = im[m];
            ull n0r = f2fma(nAw, p1i, f2fma(Az, p1r, f2fma(nAy, p0i, f2mul(Ax, p0r))));
            ull n0i = f2fma(Aw,  p1r, f2fma(Az, p1i, f2fma(Ay,  p0r, f2mul(Ax, p0i))));
            ull n1r = f2fma(nBw, p1i, f2fma(Bz, p1r, f2fma(nBy, p0i, f2mul(Bx, p0r))));
            ull n1i = f2fma(Bw,  p1r, f2fma(Bz, p1i, f2fma(By,  p0r, f2mul(Bx, p0i))));
            re[k] = n0r; im[k] = n0i; re[m] = n1r; im[m] = n1i;
        }
}

template<int NB, int JC, int JT>
__device__ __forceinline__ void cnotP(ull* re, ull* im) {
#pragma unroll
    for (int k = 0; k < (1 << NB); ++k)
        if ((k & (1 << JC)) && !(k & (1 << JT))) {
            const int m = k | (1 << JT);
            ull t = re[k]; re[k] = re[m]; re[m] = t;
            t = im[k]; im[k] = im[m]; im[m] = t;
        }
}

// predicated half-swap: CNOT whose ctrl bit is a thread-base bit
template<int NB, int JT>
__device__ __forceinline__ void cswapHalf(ull* re, ull* im, bool pred) {
    if (pred) {
#pragma unroll
        for (int k = 0; k < (1 << NB); ++k)
            if (!(k & (1 << JT))) {
                const int m = k | (1 << JT);
                ull t = re[k]; re[k] = re[m]; re[m] = t;
                t = im[k]; im[k] = im[m]; im[m] = t;
            }
    }
}

template<int J0,int J1,int J2,int J3>
__device__ __forceinline__ void load16(ull* re, ull* im,
                                       const ull* reP, const ull* imP, int pjb) {
#pragma unroll
    for (int k = 0; k < 16; ++k) {
        int joff = ((k&1)?(1<<J0):0) | ((k&2)?(1<<J1):0)
                 | ((k&4)?(1<<J2):0) | ((k&8)?(1<<J3):0);
        int a = pjb ^ (joff ^ ((joff >> 4) & 15));
        re[k] = reP[a]; im[k] = imP[a];
    }
}
template<int J0,int J1,int J2,int J3>
__device__ __forceinline__ void store16(const ull* re, const ull* im,
                                        ull* reP, ull* imP, int pjb) {
#pragma unroll
    for (int k = 0; k < 16; ++k) {
        int joff = ((k&1)?(1<<J0):0) | ((k&2)?(1<<J1):0)
                 | ((k&4)?(1<<J2):0) | ((k&8)?(1<<J3):0);
        int a = pjb ^ (joff ^ ((joff >> 4) & 15));
        reP[a] = re[k]; imP[a] = im[k];
    }
}

__device__ __forceinline__ float2 cmulf(float2 a, float2 b) {
    return make_float2(a.x*b.x - a.y*b.y, a.x*b.y + a.y*b.x);
}

// ---------------------------------------------------------------------------
// Gate passes for one layer (layers 2..4). Wire w <-> amp bit (13-w).
// P1 cube amp{10..13}=j{9..12}: gates w0..3 + CNOT(0,1)(1,2)(2,3)
// P2 cube amp{6..9} =j{5..8} : gates w4..7 + CNOT(3,4)[pred](4,5)(5,6)(6,7)
// P3 cube amp{2..5} =j{1..4} : gates w8..11 + CNOT(7,8)[pred](8,9)(9,10)(10,11)
// P4 cube amp{0(lane),1,13}  : gates w12,13 + CNOT(11,12)[pred](12,13)(13,0)
// ---------------------------------------------------------------------------
__device__ __forceinline__ void pass1(ull* reP, ull* imP, const float* gl, int tid) {
    int pjb = swz4(tid);
    ull re[16], im[16];
    load16<9,10,11,12>(re, im, reP, imP, pjb);
    gateP<4,3>(re, im, (const ull*)(gl + 0*24));   // w0 (amp13)
    gateP<4,2>(re, im, (const ull*)(gl + 1*24));   // w1 (amp12)
    gateP<4,1>(re, im, (const ull*)(gl + 2*24));   // w2 (amp11)
    gateP<4,0>(re, im, (const ull*)(gl + 3*24));   // w3 (amp10)
    cnotP<4,3,2>(re, im); cnotP<4,2,1>(re, im); cnotP<4,1,0>(re, im);
    store16<9,10,11,12>(re, im, reP, imP, pjb);
}
__device__ __forceinline__ void pass2(ull* reP, ull* imP, const float* gl, int tid) {
    int base = (tid & 31) | ((tid >> 5) << 9);
    int pjb = swz4(base);
    ull re[16], im[16];
    load16<5,6,7,8>(re, im, reP, imP, pjb);
    gateP<4,3>(re, im, (const ull*)(gl + 4*24));   // w4 (amp9)
    gateP<4,2>(re, im, (const ull*)(gl + 5*24));   // w5 (amp8)
    gateP<4,1>(re, im, (const ull*)(gl + 6*24));   // w6 (amp7)
    gateP<4,0>(re, im, (const ull*)(gl + 7*24));   // w7 (amp6)
    cswapHalf<4,3>(re, im, (tid >> 5) & 1);        // CNOT(3,4): ctrl amp10=j9=tid5
    cnotP<4,3,2>(re, im); cnotP<4,2,1>(re, im); cnotP<4,1,0>(re, im);
    store16<5,6,7,8>(re, im, reP, imP, pjb);
}
__device__ __forceinline__ void pass3(ull* reP, ull* imP, const float* gl, int tid) {
    int base = (tid & 1) | ((tid >> 1) << 5);
    int pjb = swz4(base);
    ull re[16], im[16];
    load16<1,2,3,4>(re, im, reP, imP, pjb);
    gateP<4,3>(re, im, (const ull*)(gl + 8*24));   // w8 (amp5)
    gateP<4,2>(re, im, (const ull*)(gl + 9*24));   // w9 (amp4)
    gateP<4,1>(re, im, (const ull*)(gl + 10*24));  // w10 (amp3)
    gateP<4,0>(re, im, (const ull*)(gl + 11*24));  // w11 (amp2)
    cswapHalf<4,3>(re, im, (tid >> 1) & 1);        // CNOT(7,8): ctrl amp6=j5=tid1
    cnotP<4,3,2>(re, im); cnotP<4,2,1>(re, im); cnotP<4,1,0>(re, im);
    store16<1,2,3,4>(re, im, reP, imP, pjb);
}

// P4 body on a 4-entry packed cube (k&1->amp1, k&2->amp13, lanes->amp0)
__device__ __forceinline__ void p4body(ull* re, ull* im, const float* gl, bool pred) {
    gateP<2,0>(re, im, (const ull*)(gl + 12*24));  // w12 (amp1)
    const ull* g13 = (const ull*)(gl + 13*24);
    ull C1 = g13[0], C2 = g13[1], nC2 = g13[2],
        C3 = g13[3], C4 = g13[4], nC4 = g13[5];
#pragma unroll
    for (int k = 0; k < 4; ++k) {                  // w13 (amp0, intra-lane)
        ull qr = lswap(re[k]), qi = lswap(im[k]);
        ull nr = f2fma(C4,  qi, f2fma(C3, qr, f2fma(C2,  im[k], f2mul(C1, re[k]))));
        ull ni = f2fma(nC4, qr, f2fma(C3, qi, f2fma(nC2, re[k], f2mul(C1, im[k]))));
        re[k] = nr; im[k] = ni;
    }
    // CNOT(11,12): ctrl amp2 (thread bit), tgt amp1 (cube bit0)
    if (pred) {
        ull t = re[0]; re[0] = re[1]; re[1] = t;  t = im[0]; im[0] = im[1]; im[1] = t;
        t = re[2]; re[2] = re[3]; re[3] = t;      t = im[2]; im[2] = im[3]; im[3] = t;
    }
    // CNOT(12,13): ctrl amp1 (k&1) -> lane swap (amp0)
    re[1] = lswap(re[1]); im[1] = lswap(im[1]);
    re[3] = lswap(re[3]); im[3] = lswap(im[3]);
    // CNOT(13,0): ctrl amp0 (hi lane) -> swap amp13 (k&2) for hi lanes
#pragma unroll
    for (int k1 = 0; k1 < 2; ++k1) {
        float alo, ahi, blo, bhi;
        upk(re[k1], alo, ahi); upk(re[k1|2], blo, bhi);
        re[k1] = pk(alo, bhi); re[k1|2] = pk(blo, ahi);
        upk(im[k1], alo, ahi); upk(im[k1|2], blo, bhi);
        im[k1] = pk(alo, bhi); im[k1|2] = pk(blo, ahi);
    }
}

// ---------------------------------------------------------------------------
// Kernel. SMEM (floats): re[16384] | im[16384] | gmat[42*24] | enc[28]
//                       | ftab[56] | red[240]
// ---------------------------------------------------------------------------
__global__ void __launch_bounds__(NT, 1)
vqc_kernel(const float* __restrict__ x,    const float* __restrict__ w_in,
           const float* __restrict__ b_in, const float* __restrict__ wts,
           const float* __restrict__ w_out,const float* __restrict__ b_out,
           float* __restrict__ out)
{
    extern __shared__ float smem[];
    float* reF   = smem;
    float* imF   = smem + DIM;
    float* gmat  = smem + 2 * DIM;          // 42 gates * 24 = 1008
    float* enc   = gmat + 42 * 24;          // 28
    float* ftabF = enc + 28;                // 56 (14 amp-bits x 2 x complex)
    float* red   = ftabF + 56;              // 240
    ull* reP = (ull*)reF;
    ull* imP = (ull*)imF;
    float2* ftab = (float2*)ftabF;          // ftab[t*2 + bit]

    const int b = blockIdx.x, tid = threadIdx.x;

    // --- input layer + encoding cos/sin (half-angle = pi*v/2)
    if (tid < NQ) {
        float acc = b_in[tid];
#pragma unroll
        for (int s2 = 0; s2 < SEQL; ++s2) acc += x[b*SEQL + s2] * w_in[tid*SEQL + s2];
        enc[2*tid]     = cospif(0.5f * acc);
        enc[2*tid + 1] = sinpif(0.5f * acc);
    }
    __syncthreads();

    // --- fused U = RZ*RY*RX per (layer, wire); layer0 folded into ftab
    if (tid < NQ * NL) {
        int i = tid % NQ, j = tid / NQ;
        const float* w = wts + (i*NL + j)*3;
        float cx = cosf(0.5f*w[0]), sx = sinf(0.5f*w[0]);
        float cy = cosf(0.5f*w[1]), sy = sinf(0.5f*w[1]);
        float cz = cosf(0.5f*w[2]), sz = sinf(0.5f*w[2]);
        float2 m00 = make_float2( cy*cx,  sy*sx);
        float2 m01 = make_float2(-sy*cx, -cy*sx);
        float2 m10 = make_float2( sy*cx, -cy*sx);
        float2 m11 = make_float2( cy*cx, -sy*sx);
        float2 e0 = make_float2(cz, -sz), e1 = make_float2(cz, sz);
        float2 u00 = cmulf(e0, m00), u01 = cmulf(e0, m01);
        float2 u10 = cmulf(e1, m10), u11 = cmulf(e1, m11);
        if (j == 0) {
            // layer-1 gate folded into per-wire product factor: v = U * (c, s)^T
            float c = enc[2*i], s = enc[2*i+1];
            int t = 13 - i;   // amp bit
            ftab[t*2 + 0] = make_float2(u00.x*c + u01.x*s, u00.y*c + u01.y*s);
            ftab[t*2 + 1] = make_float2(u10.x*c + u11.x*s, u10.y*c + u11.y*s);
        } else {
            float* g = gmat + ((j-1)*NQ + i)*24;
            if (i < 13) {
                float c[12] = { u00.x, u00.y, -u00.y, u01.x, u01.y, -u01.y,
                                u10.x, u10.y, -u10.y, u11.x, u11.y, -u11.y };
#pragma unroll
                for (int q = 0; q < 12; ++q) { g[2*q] = c[q]; g[2*q+1] = c[q]; }
            } else {
                g[0] = u00.x;  g[1] = u11.x;    // C1
                g[2] = -u00.y; g[3] = -u11.y;   // C2
                g[4] = u00.y;  g[5] = u11.y;    // nC2
                g[6] = u01.x;  g[7] = u10.x;    // C3
                g[8] = -u01.y; g[9] = -u10.y;   // C4
                g[10] = u01.y; g[11] = u10.y;   // nC4
            }
        }
    }
    __syncthreads();

    // --- init: state AFTER layer 1 (gates folded into ftab, CNOT ring folded
    // via relabel q = R^{-1}(p) = (p ^ (p>>1)) ^ ((p&1)*0x3000)).
    {
        // low product: q bits 0..7 depend only on tid
        int ql = (tid ^ (tid >> 1)) & 0xFF;
        float2 lowp = make_float2(1.f, 0.f);
#pragma unroll
        for (int t = 0; t < 8; ++t)
            lowp = cmulf(lowp, ftab[t*2 + ((ql >> t) & 1)]);
        // preload factors for amp bits 8..13
        float2 F0[6], F1[6];
#pragma unroll
        for (int t = 0; t < 6; ++t) { F0[t] = ftab[(8+t)*2]; F1[t] = ftab[(8+t)*2+1]; }
        int t0 = tid & 1, t8 = (tid >> 8) & 1;
#pragma unroll
        for (int k = 0; k < DIM/NT; ++k) {
            int q8  = t8 ^ (k & 1);
            int q9  = (k ^ (k >> 1)) & 1;
            int q10 = ((k >> 1) ^ (k >> 2)) & 1;
            int q11 = ((k >> 2) ^ (k >> 3)) & 1;
            int q12 = (((k >> 3) ^ (k >> 4)) & 1) ^ t0;
            int q13 = ((k >> 4) & 1) ^ t0;
            float2 p = lowp;
            p = cmulf(p, q8  ? F1[0] : F0[0]);
            p = cmulf(p, q9  ? F1[1] : F0[1]);
            p = cmulf(p, q10 ? F1[2] : F0[2]);
            p = cmulf(p, q11 ? F1[3] : F0[3]);
            p = cmulf(p, q12 ? F1[4] : F0[4]);
            p = cmulf(p, q13 ? F1[5] : F0[5]);
            int idx = tid + NT*k;
            int a = 2*swz4(idx >> 1) + (idx & 1);
            reF[a] = p.x; imF[a] = p.y;
        }
    }
    __syncthreads();

    // --- layers 2..4 ---
#pragma unroll 1
    for (int jl = 0; jl < 2; ++jl) {
        const float* gl = gmat + jl * NQ * 24;
        pass1(reP, imP, gl, tid);  __syncthreads();
        pass2(reP, imP, gl, tid);  __syncthreads();
        pass3(reP, imP, gl, tid);  __syncthreads();
#pragma unroll 1
        for (int rep = 0; rep < 4; ++rep) {   // P4 with store
            int v = tid + NT*rep;
            int jb = swz4(v << 1);
            int a0 = jb, a1 = jb ^ 1, a2 = jb ^ 4096, a3 = a2 ^ 1;
            ull re[4], im[4];
            re[0] = reP[a0]; im[0] = imP[a0];
            re[1] = reP[a1]; im[1] = imP[a1];
            re[2] = reP[a2]; im[2] = imP[a2];
            re[3] = reP[a3]; im[3] = imP[a3];
            p4body(re, im, gl, v & 1);
            reP[a0] = re[0]; imP[a0] = im[0];
            reP[a1] = re[1]; imP[a1] = im[1];
            reP[a2] = re[2]; imP[a2] = im[2];
            reP[a3] = re[3]; imP[a3] = im[3];
        }
        __syncthreads();
    }

    // layer 4: P1-P3, then P4 fused with Z readout (no final store)
    {
        const float* gl = gmat + 2 * NQ * 24;
        pass1(reP, imP, gl, tid);  __syncthreads();
        pass2(reP, imP, gl, tid);  __syncthreads();
        pass3(reP, imP, gl, tid);  __syncthreads();

        float z[NQ];
#pragma unroll
        for (int w = 0; w < NQ; ++w) z[w] = 0.f;
#pragma unroll 1
        for (int rep = 0; rep < 4; ++rep) {
            int v = tid + NT*rep;
            int jb = swz4(v << 1);
            int a0 = jb, a1 = jb ^ 1, a2 = jb ^ 4096, a3 = a2 ^ 1;
            ull re[4], im[4];
            re[0] = reP[a0]; im[0] = imP[a0];
            re[1] = reP[a1]; im[1] = imP[a1];
            re[2] = reP[a2]; im[2] = imP[a2];
            re[3] = reP[a3]; im[3] = imP[a3];
            p4body(re, im, gl, v & 1);
#pragma unroll
            for (int k = 0; k < 4; ++k) {
                float rlo, rhi, ilo, ihi;
                upk(re[k], rlo, rhi); upk(im[k], ilo, ihi);
                float plo = rlo*rlo + ilo*ilo;
                float phi = rhi*rhi + ihi*ihi;
                float ps = plo + phi;
                // amp bits: amp1=k&1, amp13=(k>>1)&1, amp2..12 = v bits 0..10
                int pb = ((k & 1) << 1) | (((k >> 1) & 1) << 13) | (v << 2);
#pragma unroll
                for (int w = 0; w < 13; ++w)
                    z[w] += (pb & (1 << (13 - w))) ? -ps : ps;
                z[13] += plo - phi;   // wire13 <-> amp0 (lane)
            }
        }

        // warp reduce + block reduce + output
#pragma unroll
        for (int w = 0; w < NQ; ++w)
#pragma unroll
            for (int o = 16; o; o >>= 1)
                z[w] += __shfl_xor_sync(0xffffffffu, z[w], o);

        __syncthreads();
        if ((tid & 31) == 0) {
            int wr = tid >> 5;
#pragma unroll
            for (int w = 0; w < NQ; ++w) red[wr*NQ + w] = z[w];
        }
        __syncthreads();
        if (tid < NQ) {
            float s = 0.f;
#pragma unroll
            for (int wr = 0; wr < NT/32; ++wr) s += red[wr*NQ + tid];
            red[224 + tid] = s * w_out[tid];
        }
        __syncthreads();
        if (tid == 0) {
            float o = b_out[0];
#pragma unroll
            for (int w = 0; w < NQ; ++w) o += red[224 + w];
            out[b] = o;
        }
    }
}

// ---------------------------------------------------------------------------
extern "C" void kernel_launch(void* const* d_in, const int* in_sizes, int n_in,
                              void* d_out, int out_size)
{
    const float* x     = (const float*)d_in[0];
    const float* w_in  = (const float*)d_in[1];
    const float* b_in  = (const float*)d_in[2];
    const float* wts   = (const float*)d_in[3];
    const float* w_out = (const float*)d_in[4];
    const float* b_out = (const float*)d_in[5];
    float* out = (float*)d_out;

    const int B = in_sizes[0] / SEQL;                       // 1024
    const int smem = (2*DIM + 42*24 + 28 + 56 + 240) * (int)sizeof(float);

    cudaFuncSetAttribute(vqc_kernel, cudaFuncAttributeMaxDynamicSharedMemorySize, smem);
    vqc_kernel<<<B, NT, smem>>>(x, w_in, b_in, wts, w_out, b_out, out);
}

// round 8
// speedup vs baseline: 1.3491x; 1.0300x over previous
#include <cuda_runtime.h>
#include <cstdint>

#define NQ   14
#define NL   4
#define DIM  16384          // 2^14
#define NT   512            // threads per CTA (16 warps)
#define SEQL 8

typedef unsigned long long ull;

// ---------------------------------------------------------------------------
// Packed f32x2 primitives
// ---------------------------------------------------------------------------
__device__ __forceinline__ ull f2mul(ull a, ull b) {
    ull d; asm("mul.rn.f32x2 %0, %1, %2;" : "=l"(d) : "l"(a), "l"(b)); return d;
}
__device__ __forceinline__ ull f2fma(ull a, ull b, ull c) {
    ull d; asm("fma.rn.f32x2 %0, %1, %2, %3;" : "=l"(d) : "l"(a), "l"(b), "l"(c)); return d;
}
__device__ __forceinline__ ull f2add(ull a, ull b) {
    ull d; asm("add.rn.f32x2 %0, %1, %2;" : "=l"(d) : "l"(a), "l"(b)); return d;
}
__device__ __forceinline__ ull pk(float lo, float hi) {
    ull r; asm("mov.b64 %0, {%1, %2};" : "=l"(r) : "f"(lo), "f"(hi)); return r;
}
__device__ __forceinline__ void upk(ull v, float& lo, float& hi) {
    asm("mov.b64 {%0, %1}, %2;" : "=f"(lo), "=f"(hi) : "l"(v));
}
__device__ __forceinline__ ull lswap(ull v) {
    float lo, hi; upk(v, lo, hi); return pk(hi, lo);
}

// ---------------------------------------------------------------------------
// Layout: SoA planes re/im; amp i at 4B-index 2*swz4(i>>1) + (i&1).
// swz4 (pair-index space): j ^ ((j>>4)&15) — folds j4..7 into j0..3.
// ---------------------------------------------------------------------------
__device__ __forceinline__ int swz4(int j) { return j ^ ((j >> 4) & 15); }

// ---------------------------------------------------------------------------
// Packed register-cube primitives (duplicated-pair coeff tables, 24 floats):
//  [Ax Ay -Ay Az Aw -Aw Bx By -By Bz Bw -Bw], A=row0(u00,u01), B=row1(u10,u11)
// ---------------------------------------------------------------------------
template<int NB, int J>
__device__ __forceinline__ void gateP(ull* re, ull* im, const ull* g) {
    ull Ax = g[0], Ay = g[1], nAy = g[2], Az = g[3], Aw = g[4], nAw = g[5];
    ull Bx = g[6], By = g[7], nBy = g[8], Bz = g[9], Bw = g[10], nBw = g[11];
#pragma unroll
    for (int k = 0; k < (1 << NB); ++k)
        if (!(k & (1 << J))) {
            const int m = k | (1 << J);
            ull p0r = re[k], p0i = im[k], p1r = re[m], p1i = im[m];
            ull n0r = f2fma(nAw, p1i, f2fma(Az, p1r, f2fma(nAy, p0i, f2mul(Ax, p0r))));
            ull n0i = f2fma(Aw,  p1r, f2fma(Az, p1i, f2fma(Ay,  p0r, f2mul(Ax, p0i))));
            ull n1r = f2fma(nBw, p1i, f2fma(Bz, p1r, f2fma(nBy, p0i, f2mul(Bx, p0r))));
            ull n1i = f2fma(Bw,  p1r, f2fma(Bz, p1i, f2fma(By,  p0r, f2mul(Bx, p0i))));
            re[k] = n0r; im[k] = n0i; re[m] = n1r; im[m] = n1i;
        }
}

template<int NB, int JC, int JT>
__device__ __forceinline__ void cnotP(ull* re, ull* im) {
#pragma unroll
    for (int k = 0; k < (1 << NB); ++k)
        if ((k & (1 << JC)) && !(k & (1 << JT))) {
            const int m = k | (1 << JT);
            ull t = re[k]; re[k] = re[m]; re[m] = t;
            t = im[k]; im[k] = im[m]; im[m] = t;
        }
}

template<int NB, int JT>
__device__ __forceinline__ void cswapHalf(ull* re, ull* im, bool pred) {
    if (pred) {
#pragma unroll
        for (int k = 0; k < (1 << NB); ++k)
            if (!(k & (1 << JT))) {
                const int m = k | (1 << JT);
                ull t = re[k]; re[k] = re[m]; re[m] = t;
                t = im[k]; im[k] = im[m]; im[m] = t;
            }
    }
}

template<int J0,int J1,int J2,int J3>
__device__ __forceinline__ void load16(ull* re, ull* im,
                                       const ull* reP, const ull* imP, int pjb) {
#pragma unroll
    for (int k = 0; k < 16; ++k) {
        int joff = ((k&1)?(1<<J0):0) | ((k&2)?(1<<J1):0)
                 | ((k&4)?(1<<J2):0) | ((k&8)?(1<<J3):0);
        int a = pjb ^ (joff ^ ((joff >> 4) & 15));
        re[k] = reP[a]; im[k] = imP[a];
    }
}
template<int J0,int J1,int J2,int J3>
__device__ __forceinline__ void store16(const ull* re, const ull* im,
                                        ull* reP, ull* imP, int pjb) {
#pragma unroll
    for (int k = 0; k < 16; ++k) {
        int joff = ((k&1)?(1<<J0):0) | ((k&2)?(1<<J1):0)
                 | ((k&4)?(1<<J2):0) | ((k&8)?(1<<J3):0);
        int a = pjb ^ (joff ^ ((joff >> 4) & 15));
        reP[a] = re[k]; imP[a] = im[k];
    }
}

__device__ __forceinline__ float2 cmulf(float2 a, float2 b) {
    return make_float2(a.x*b.x - a.y*b.y, a.x*b.y + a.y*b.x);
}

// intra-lane butterfly for wire 13 (amp0) on all 16 packed entries
__device__ __forceinline__ void gateLaneAll(ull* re, ull* im, const ull* g13) {
    ull C1 = g13[0], C2 = g13[1], nC2 = g13[2],
        C3 = g13[3], C4 = g13[4], nC4 = g13[5];
#pragma unroll
    for (int k = 0; k < 16; ++k) {
        ull qr = lswap(re[k]), qi = lswap(im[k]);
        ull nr = f2fma(C4,  qi, f2fma(C3, qr, f2fma(C2,  im[k], f2mul(C1, re[k]))));
        ull ni = f2fma(nC4, qr, f2fma(C3, qi, f2fma(nC2, re[k], f2mul(C1, im[k]))));
        re[k] = nr; im[k] = ni;
    }
}

// carried CNOT(13,0): ctrl amp0 (hi lane), tgt amp13 (cube bit 3)
__device__ __forceinline__ void carriedSwap(ull* re, ull* im) {
#pragma unroll
    for (int k1 = 0; k1 < 8; ++k1) {
        float alo, ahi, blo, bhi;
        upk(re[k1], alo, ahi); upk(re[k1|8], blo, bhi);
        re[k1] = pk(alo, bhi); re[k1|8] = pk(blo, ahi);
        upk(im[k1], alo, ahi); upk(im[k1|8], blo, bhi);
        im[k1] = pk(alo, bhi); im[k1|8] = pk(blo, ahi);
    }
}

// wire-8 shuffle butterfly (partner = tid^1), row table preselected
__device__ __forceinline__ void gateShfl(ull* re, ull* im, const ull* gr) {
    ull Ax = gr[0], Ay = gr[1], nAy = gr[2], Az = gr[3], Aw = gr[4], nAw = gr[5];
#pragma unroll
    for (int k = 0; k < 16; ++k) {
        ull qr = __shfl_xor_sync(0xffffffffu, re[k], 1);
        ull qi = __shfl_xor_sync(0xffffffffu, im[k], 1);
        ull nr = f2fma(nAw, qi, f2fma(Az, qr, f2fma(nAy, im[k], f2mul(Ax, re[k]))));
        ull ni = f2fma(Aw,  qr, f2fma(Az, qi, f2fma(Ay,  re[k], f2mul(Ax, im[k]))));
        re[k] = nr; im[k] = ni;
    }
}

// ---------------------------------------------------------------------------
// Passes. Wire w <-> amp bit (13-w).
// A: cube j{9..12}=amp{10..13}+lane: [carry (13,0)], w0..w3, w13, CNOT(0,1)(1,2)(2,3)
// B: cube j{5..8}=amp{6..9}: w4..w7, CNOT(3,4)pred,(4,5)(5,6)(6,7)
// C: cube j{0..3}=amp{1..4}, tid0=amp5: w8(shfl,+CNOT(7,8) fused), w9..w12,
//    CNOT(8,9)pred,(9,10)(10,11)(11,12),(12,13)lane; (13,0) carried out
// ---------------------------------------------------------------------------
__device__ __forceinline__ void pass_a(ull* reP, ull* imP, const float* gl,
                                       int tid, bool carry) {
    int pjb = swz4(tid);
    ull re[16], im[16];
    load16<9,10,11,12>(re, im, reP, imP, pjb);
    if (carry) carriedSwap(re, im);
    gateP<4,3>(re, im, (const ull*)(gl + 0*24));   // w0 (amp13)
    gateP<4,2>(re, im, (const ull*)(gl + 1*24));   // w1 (amp12)
    gateP<4,1>(re, im, (const ull*)(gl + 2*24));   // w2 (amp11)
    gateP<4,0>(re, im, (const ull*)(gl + 3*24));   // w3 (amp10)
    gateLaneAll(re, im, (const ull*)(gl + 13*24)); // w13 (amp0)
    cnotP<4,3,2>(re, im); cnotP<4,2,1>(re, im); cnotP<4,1,0>(re, im);
    store16<9,10,11,12>(re, im, reP, imP, pjb);
}
__device__ __forceinline__ void pass_b(ull* reP, ull* imP, const float* gl, int tid) {
    int base = (tid & 31) | ((tid >> 5) << 9);
    int pjb = swz4(base);
    ull re[16], im[16];
    load16<5,6,7,8>(re, im, reP, imP, pjb);
    gateP<4,3>(re, im, (const ull*)(gl + 4*24));   // w4 (amp9)
    gateP<4,2>(re, im, (const ull*)(gl + 5*24));   // w5 (amp8)
    gateP<4,1>(re, im, (const ull*)(gl + 6*24));   // w6 (amp7)
    gateP<4,0>(re, im, (const ull*)(gl + 7*24));   // w7 (amp6)
    cswapHalf<4,3>(re, im, (tid >> 5) & 1);        // CNOT(3,4): ctrl amp10=j9=tid5
    cnotP<4,3,2>(re, im); cnotP<4,2,1>(re, im); cnotP<4,1,0>(re, im);
    store16<5,6,7,8>(re, im, reP, imP, pjb);
}
__device__ __forceinline__ void pass_c(ull* reP, ull* imP, const float* gl,
                                       const float* g8, int tid) {
    int pjb = swz4(tid << 4);
    ull re[16], im[16];
    load16<0,1,2,3>(re, im, reP, imP, pjb);
    // w8 (amp5 = tid bit0) with CNOT(7,8) fused: sel = amp5 | (amp6<<1) = tid&3
    gateShfl(re, im, (const ull*)(g8 + (tid & 3) * 12));
    gateP<4,3>(re, im, (const ull*)(gl + 9*24));   // w9 (amp4)
    gateP<4,2>(re, im, (const ull*)(gl + 10*24));  // w10 (amp3)
    gateP<4,1>(re, im, (const ull*)(gl + 11*24));  // w11 (amp2)
    gateP<4,0>(re, im, (const ull*)(gl + 12*24));  // w12 (amp1)
    cswapHalf<4,3>(re, im, tid & 1);               // CNOT(8,9): ctrl amp5=tid0
    cnotP<4,3,2>(re, im); cnotP<4,2,1>(re, im); cnotP<4,1,0>(re, im);
    // CNOT(12,13): ctrl amp1 (cube bit0), tgt amp0 (lane)
#pragma unroll
    for (int k = 1; k < 16; k += 2) { re[k] = lswap(re[k]); im[k] = lswap(im[k]); }
    store16<0,1,2,3>(re, im, reP, imP, pjb);
    // CNOT(13,0) carried to next layer's pass A
}

// ---------------------------------------------------------------------------
// Kernel. SMEM (floats): re[16384] | im[16384] | gmat[42*24] | g8tab[3*4*12]
//                       | enc[28] | red[240]
// ---------------------------------------------------------------------------
__global__ void __launch_bounds__(NT, 1)
vqc_kernel(const float* __restrict__ x,    const float* __restrict__ w_in,
           const float* __restrict__ b_in, const float* __restrict__ wts,
           const float* __restrict__ w_out,const float* __restrict__ b_out,
           float* __restrict__ out)
{
    extern __shared__ float smem[];
    float* reF   = smem;
    float* imF   = smem + DIM;
    float* gmat  = smem + 2 * DIM;          // 1008
    float* g8tab = gmat + 42 * 24;          // 144
    float* enc   = g8tab + 144;             // 28
    float* red   = enc + 28;                // 240
    ull* reP = (ull*)reF;
    ull* imP = (ull*)imF;
    float2* ftab = (float2*)red;            // reuse red for init factor table (56 floats)

    const int b = blockIdx.x, tid = threadIdx.x;

    if (tid < NQ) {
        float acc = b_in[tid];
#pragma unroll
        for (int s2 = 0; s2 < SEQL; ++s2) acc += x[b*SEQL + s2] * w_in[tid*SEQL + s2];
        enc[2*tid]     = cospif(0.5f * acc);
        enc[2*tid + 1] = sinpif(0.5f * acc);
    }
    __syncthreads();

    // --- fused U = RZ*RY*RX per (layer, wire); layer1 folded; layer4 drops RZ
    if (tid < NQ * NL) {
        int i = tid % NQ, j = tid / NQ;
        const float* w = wts + (i*NL + j)*3;
        float cx = cosf(0.5f*w[0]), sx = sinf(0.5f*w[0]);
        float cy = cosf(0.5f*w[1]), sy = sinf(0.5f*w[1]);
        float cz = cosf(0.5f*w[2]), sz = sinf(0.5f*w[2]);
        if (j == 3) { cz = 1.f; sz = 0.f; }   // final-layer RZ is phase-only
        float2 m00 = make_float2( cy*cx,  sy*sx);
        float2 m01 = make_float2(-sy*cx, -cy*sx);
        float2 m10 = make_float2( sy*cx, -cy*sx);
        float2 m11 = make_float2( cy*cx, -sy*sx);
        float2 e0 = make_float2(cz, -sz), e1 = make_float2(cz, sz);
        float2 u00 = cmulf(e0, m00), u01 = cmulf(e0, m01);
        float2 u10 = cmulf(e1, m10), u11 = cmulf(e1, m11);
        if (j == 0) {
            float c = enc[2*i], s = enc[2*i+1];
            int t = 13 - i;
            ftab[t*2 + 0] = make_float2(u00.x*c + u01.x*s, u00.y*c + u01.y*s);
            ftab[t*2 + 1] = make_float2(u10.x*c + u11.x*s, u10.y*c + u11.y*s);
        } else if (i == 8) {
            // 4 row tables for shuffle gate: sel = amp5 | (amp6<<1)
            float2 Ca[4] = { u00, u11, u10, u01 };
            float2 Cb[4] = { u01, u10, u11, u00 };
#pragma unroll
            for (int s4 = 0; s4 < 4; ++s4) {
                float* r = g8tab + ((j-1)*4 + s4)*12;
                r[0]=Ca[s4].x; r[1]=Ca[s4].x;  r[2]=Ca[s4].y; r[3]=Ca[s4].y;
                r[4]=-Ca[s4].y; r[5]=-Ca[s4].y; r[6]=Cb[s4].x; r[7]=Cb[s4].x;
                r[8]=Cb[s4].y; r[9]=Cb[s4].y;  r[10]=-Cb[s4].y; r[11]=-Cb[s4].y;
            }
        } else {
            float* g = gmat + ((j-1)*NQ + i)*24;
            if (i < 13) {
                float c[12] = { u00.x, u00.y, -u00.y, u01.x, u01.y, -u01.y,
                                u10.x, u10.y, -u10.y, u11.x, u11.y, -u11.y };
#pragma unroll
                for (int q = 0; q < 12; ++q) { g[2*q] = c[q]; g[2*q+1] = c[q]; }
            } else {
                g[0] = u00.x;  g[1] = u11.x;
                g[2] = -u00.y; g[3] = -u11.y;
                g[4] = u00.y;  g[5] = u11.y;
                g[6] = u01.x;  g[7] = u10.x;
                g[8] = -u01.y; g[9] = -u10.y;
                g[10] = u01.y; g[11] = u10.y;
            }
        }
    }
    __syncthreads();

    // --- init: state AFTER layer 1 (ring folded via q = (p^(p>>1)) ^ ((p&1)*0x3000))
    {
        int ql = (tid ^ (tid >> 1)) & 0xFF;
        float2 lowp = make_float2(1.f, 0.f);
#pragma unroll
        for (int t = 0; t < 8; ++t)
            lowp = cmulf(lowp, ftab[t*2 + ((ql >> t) & 1)]);
        float2 F0[6], F1[6];
#pragma unroll
        for (int t = 0; t < 6; ++t) { F0[t] = ftab[(8+t)*2]; F1[t] = ftab[(8+t)*2+1]; }
        int t0 = tid & 1, t8 = (tid >> 8) & 1;
#pragma unroll
        for (int k = 0; k < DIM/NT; ++k) {
            int q8  = t8 ^ (k & 1);
            int q9  = (k ^ (k >> 1)) & 1;
            int q10 = ((k >> 1) ^ (k >> 2)) & 1;
            int q11 = ((k >> 2) ^ (k >> 3)) & 1;
            int q12 = (((k >> 3) ^ (k >> 4)) & 1) ^ t0;
            int q13 = ((k >> 4) & 1) ^ t0;
            float2 p = lowp;
            p = cmulf(p, q8  ? F1[0] : F0[0]);
            p = cmulf(p, q9  ? F1[1] : F0[1]);
            p = cmulf(p, q10 ? F1[2] : F0[2]);
            p = cmulf(p, q11 ? F1[3] : F0[3]);
            p = cmulf(p, q12 ? F1[4] : F0[4]);
            p = cmulf(p, q13 ? F1[5] : F0[5]);
            int idx = tid + NT*k;
            int a = 2*swz4(idx >> 1) + (idx & 1);
            reF[a] = p.x; imF[a] = p.y;
        }
    }
    __syncthreads();

    // --- layers 2, 3 ---
#pragma unroll 1
    for (int jl = 0; jl < 2; ++jl) {
        const float* gl = gmat + jl * NQ * 24;
        const float* g8 = g8tab + jl * 48;
        pass_a(reP, imP, gl, tid, jl > 0);  __syncthreads();
        pass_b(reP, imP, gl, tid);          __syncthreads();
        pass_c(reP, imP, gl, g8, tid);      __syncthreads();
    }

    // --- layer 4: A(carry), B, then C fused with readout (CNOT chain folded) ---
    {
        const float* gl = gmat + 2 * NQ * 24;
        const float* g8 = g8tab + 2 * 48;
        pass_a(reP, imP, gl, tid, true);  __syncthreads();
        pass_b(reP, imP, gl, tid);        __syncthreads();

        int pjb = swz4(tid << 4);
        ull re[16], im[16];
        load16<0,1,2,3>(re, im, reP, imP, pjb);
        gateShfl(re, im, (const ull*)(g8 + (tid & 1) * 12));  // w8, no CNOT fusion
        gateP<4,3>(re, im, (const ull*)(gl + 9*24));
        gateP<4,2>(re, im, (const ull*)(gl + 10*24));
        gateP<4,1>(re, im, (const ull*)(gl + 11*24));
        gateP<4,0>(re, im, (const ull*)(gl + 12*24));

        // Readout with residual-chain relabel for CNOT(7,8)..(12,13),(13,0).
        // Register-space bits: lane=amp0(wire13), k0..k3=amp1..4(wires 12..9),
        // tid0..tid8 = amp5..amp13 (wires 8..0).
        // Post-chain wire bits: w in 1..7 -> unchanged (tid_{8-w});
        // w8 -> tid0^tid1; w9 -> k3^tid0^tid1; w10 -> k2^k3^t01;
        // w11 -> k1^k2^k3^t01; w12 -> popc(k)^t01; w13 -> lane^popc(k)^t01;
        // w0 -> tid8 ^ (w13 bit).
        ull accP = 0, acc9 = 0, acc10 = 0, acc11 = 0, acc12 = 0;
        const ull NEG1 = 0xBF800000BF800000ull;
#pragma unroll
        for (int k = 0; k < 16; ++k) {
            ull p = f2fma(im[k], im[k], f2mul(re[k], re[k]));
            accP = f2add(accP, p);
            int k3 = (k >> 3) & 1;
            int k23 = ((k >> 2) ^ (k >> 3)) & 1;
            int k123 = ((k >> 1) ^ (k >> 2) ^ (k >> 3)) & 1;
            int kpar = __popc(k) & 1;
            acc9  = k3   ? f2fma(p, NEG1, acc9)  : f2add(acc9,  p);
            acc10 = k23  ? f2fma(p, NEG1, acc10) : f2add(acc10, p);
            acc11 = k123 ? f2fma(p, NEG1, acc11) : f2add(acc11, p);
            acc12 = kpar ? f2fma(p, NEG1, acc12) : f2add(acc12, p);
        }
        float z[NQ];
        {
            float Pl, Ph;  upk(accP, Pl, Ph);   float Ps = Pl + Ph;
            float l9, h9;  upk(acc9, l9, h9);
            float l10,h10; upk(acc10,l10,h10);
            float l11,h11; upk(acc11,l11,h11);
            float l12,h12; upk(acc12,l12,h12);
            int t01 = (tid ^ (tid >> 1)) & 1;           // tid0 ^ tid1
            float f5 = t01 ? -1.f : 1.f;
            z[1] = (tid & 128) ? -Ps : Ps;   // wire1 = tid7
            z[2] = (tid & 64)  ? -Ps : Ps;   // wire2 = tid6
            z[3] = (tid & 32)  ? -Ps : Ps;   // wire3 = tid5
            z[4] = (tid & 16)  ? -Ps : Ps;   // wire4 = tid4
            z[5] = (tid & 8)   ? -Ps : Ps;   // wire5 = tid3
            z[6] = (tid & 4)   ? -Ps : Ps;   // wire6 = tid2
            z[7] = (tid & 2)   ? -Ps : Ps;   // wire7 = tid1
            z[8] = t01 ? -Ps : Ps;           // wire8 = tid0^tid1
            z[9]  = f5 * (l9  + h9);
            z[10] = f5 * (l10 + h10);
            z[11] = f5 * (l11 + h11);
            z[12] = f5 * (l12 + h12);
            z[13] = f5 * (l12 - h12);
            z[0]  = (tid & 256) ? -z[13] : z[13];   // wire0 adds tid8
        }

#pragma unroll
        for (int w = 0; w < NQ; ++w)
#pragma unroll
            for (int o = 16; o; o >>= 1)
                z[w] += __shfl_xor_sync(0xffffffffu, z[w], o);

        __syncthreads();   // red no longer used as ftab beyond init
        if ((tid & 31) == 0) {
            int wr = tid >> 5;
#pragma unroll
            for (int w = 0; w < NQ; ++w) red[wr*NQ + w] = z[w];
        }
        __syncthreads();
        if (tid < NQ) {
            float s = 0.f;
#pragma unroll
            for (int wr = 0; wr < NT/32; ++wr) s += red[wr*NQ + tid];
            red[224 + tid] = s * w_out[tid];
        }
        __syncthreads();
        if (tid == 0) {
            float o = b_out[0];
#pragma unroll
            for (int w = 0; w < NQ; ++w) o += red[224 + w];
            out[b] = o;
        }
    }
}

// ---------------------------------------------------------------------------
extern "C" void kernel_launch(void* const* d_in, const int* in_sizes, int n_in,
                              void* d_out, int out_size)
{
    const float* x     = (const float*)d_in[0];
    const float* w_in  = (const float*)d_in[1];
    const float* b_in  = (const float*)d_in[2];
    const float* wts   = (const float*)d_in[3];
    const float* w_out = (const float*)d_in[4];
    const float* b_out = (const float*)d_in[5];
    float* out = (float*)d_out;

    const int B = in_sizes[0] / SEQL;                       // 1024
    const int smem = (2*DIM + 42*24 + 144 + 28 + 240) * (int)sizeof(float);

    cudaFuncSetAttribute(vqc_kernel, cudaFuncAttributeMaxDynamicSharedMemorySize, smem);
    vqc_kernel<<<B, NT, smem>>>(x, w_in, b_in, wts, w_out, b_out, out);
}

// round 9
// speedup vs baseline: 1.3542x; 1.0038x over previous
#include <cuda_runtime.h>
#include <cstdint>

#define NQ   14
#define NL   4
#define DIM  16384          // 2^14
#define NT   512            // threads per CTA (16 warps)
#define SEQL 8

typedef unsigned long long ull;

// ---------------------------------------------------------------------------
// Packed f32x2 primitives
// ---------------------------------------------------------------------------
__device__ __forceinline__ ull f2mul(ull a, ull b) {
    ull d; asm("mul.rn.f32x2 %0, %1, %2;" : "=l"(d) : "l"(a), "l"(b)); return d;
}
__device__ __forceinline__ ull f2fma(ull a, ull b, ull c) {
    ull d; asm("fma.rn.f32x2 %0, %1, %2, %3;" : "=l"(d) : "l"(a), "l"(b), "l"(c)); return d;
}
__device__ __forceinline__ ull f2add(ull a, ull b) {
    ull d; asm("add.rn.f32x2 %0, %1, %2;" : "=l"(d) : "l"(a), "l"(b)); return d;
}
__device__ __forceinline__ ull pk(float lo, float hi) {
    ull r; asm("mov.b64 %0, {%1, %2};" : "=l"(r) : "f"(lo), "f"(hi)); return r;
}
__device__ __forceinline__ void upk(ull v, float& lo, float& hi) {
    asm("mov.b64 {%0, %1}, %2;" : "=f"(lo), "=f"(hi) : "l"(v));
}
__device__ __forceinline__ ull lswap(ull v) {
    float lo, hi; upk(v, lo, hi); return pk(hi, lo);
}

// ---------------------------------------------------------------------------
// Layout: SoA planes re/im; amp i at 4B-index 2*swz4(i>>1) + (i&1).
// swz4 (pair-index space): j ^ ((j>>4)&15) — folds j4..7 into j0..3.
// ---------------------------------------------------------------------------
__device__ __forceinline__ int swz4(int j) { return j ^ ((j >> 4) & 15); }

// ---------------------------------------------------------------------------
// Packed register-cube primitives (duplicated-pair coeff tables, 24 floats):
//  [Ax Ay -Ay Az Aw -Aw Bx By -By Bz Bw -Bw], A=row0(u00,u01), B=row1(u10,u11)
// ---------------------------------------------------------------------------
template<int NB, int J>
__device__ __forceinline__ void gateP(ull* re, ull* im, const ull* g) {
    ull Ax = g[0], Ay = g[1], nAy = g[2], Az = g[3], Aw = g[4], nAw = g[5];
    ull Bx = g[6], By = g[7], nBy = g[8], Bz = g[9], Bw = g[10], nBw = g[11];
#pragma unroll
    for (int k = 0; k < (1 << NB); ++k)
        if (!(k & (1 << J))) {
            const int m = k | (1 << J);
            ull p0r = re[k], p0i = im[k], p1r = re[m], p1i = im[m];
            ull n0r = f2fma(nAw, p1i, f2fma(Az, p1r, f2fma(nAy, p0i, f2mul(Ax, p0r))));
            ull n0i = f2fma(Aw,  p1r, f2fma(Az, p1i, f2fma(Ay,  p0r, f2mul(Ax, p0i))));
            ull n1r = f2fma(nBw, p1i, f2fma(Bz, p1r, f2fma(nBy, p0i, f2mul(Bx, p0r))));
            ull n1i = f2fma(Bw,  p1r, f2fma(Bz, p1i, f2fma(By,  p0r, f2mul(Bx, p0i))));
            re[k] = n0r; im[k] = n0i; re[m] = n1r; im[m] = n1i;
        }
}

template<int NB, int JC, int JT>
__device__ __forceinline__ void cnotP(ull* re, ull* im) {
#pragma unroll
    for (int k = 0; k < (1 << NB); ++k)
        if ((k & (1 << JC)) && !(k & (1 << JT))) {
            const int m = k | (1 << JT);
            ull t = re[k]; re[k] = re[m]; re[m] = t;
            t = im[k]; im[k] = im[m]; im[m] = t;
        }
}

template<int NB, int JT>
__device__ __forceinline__ void cswapHalf(ull* re, ull* im, bool pred) {
    if (pred) {
#pragma unroll
        for (int k = 0; k < (1 << NB); ++k)
            if (!(k & (1 << JT))) {
                const int m = k | (1 << JT);
                ull t = re[k]; re[k] = re[m]; re[m] = t;
                t = im[k]; im[k] = im[m]; im[m] = t;
            }
    }
}

template<int J0,int J1,int J2,int J3>
__device__ __forceinline__ void load16(ull* re, ull* im,
                                       const ull* reP, const ull* imP, int pjb) {
#pragma unroll
    for (int k = 0; k < 16; ++k) {
        int joff = ((k&1)?(1<<J0):0) | ((k&2)?(1<<J1):0)
                 | ((k&4)?(1<<J2):0) | ((k&8)?(1<<J3):0);
        int a = pjb ^ (joff ^ ((joff >> 4) & 15));
        re[k] = reP[a]; im[k] = imP[a];
    }
}
template<int J0,int J1,int J2,int J3>
__device__ __forceinline__ void store16(const ull* re, const ull* im,
                                        ull* reP, ull* imP, int pjb) {
#pragma unroll
    for (int k = 0; k < 16; ++k) {
        int joff = ((k&1)?(1<<J0):0) | ((k&2)?(1<<J1):0)
                 | ((k&4)?(1<<J2):0) | ((k&8)?(1<<J3):0);
        int a = pjb ^ (joff ^ ((joff >> 4) & 15));
        reP[a] = re[k]; imP[a] = im[k];
    }
}

__device__ __forceinline__ float2 cmulf(float2 a, float2 b) {
    return make_float2(a.x*b.x - a.y*b.y, a.x*b.y + a.y*b.x);
}

// intra-lane butterfly for wire 13 (amp0) on all 16 packed entries
__device__ __forceinline__ void gateLaneAll(ull* re, ull* im, const ull* g13) {
    ull C1 = g13[0], C2 = g13[1], nC2 = g13[2],
        C3 = g13[3], C4 = g13[4], nC4 = g13[5];
#pragma unroll
    for (int k = 0; k < 16; ++k) {
        ull qr = lswap(re[k]), qi = lswap(im[k]);
        ull nr = f2fma(C4,  qi, f2fma(C3, qr, f2fma(C2,  im[k], f2mul(C1, re[k]))));
        ull ni = f2fma(nC4, qr, f2fma(C3, qi, f2fma(nC2, re[k], f2mul(C1, im[k]))));
        re[k] = nr; im[k] = ni;
    }
}

// carried CNOT(13,0): ctrl amp0 (hi lane), tgt amp13 (cube bit 3)
__device__ __forceinline__ void carriedSwap(ull* re, ull* im) {
#pragma unroll
    for (int k1 = 0; k1 < 8; ++k1) {
        float alo, ahi, blo, bhi;
        upk(re[k1], alo, ahi); upk(re[k1|8], blo, bhi);
        re[k1] = pk(alo, bhi); re[k1|8] = pk(blo, ahi);
        upk(im[k1], alo, ahi); upk(im[k1|8], blo, bhi);
        im[k1] = pk(alo, bhi); im[k1|8] = pk(blo, ahi);
    }
}

// wire-8 shuffle butterfly (partner = tid^1), row table preselected
__device__ __forceinline__ void gateShfl(ull* re, ull* im, const ull* gr) {
    ull Ax = gr[0], Ay = gr[1], nAy = gr[2], Az = gr[3], Aw = gr[4], nAw = gr[5];
#pragma unroll
    for (int k = 0; k < 16; ++k) {
        ull qr = __shfl_xor_sync(0xffffffffu, re[k], 1);
        ull qi = __shfl_xor_sync(0xffffffffu, im[k], 1);
        ull nr = f2fma(nAw, qi, f2fma(Az, qr, f2fma(nAy, im[k], f2mul(Ax, re[k]))));
        ull ni = f2fma(Aw,  qr, f2fma(Az, qi, f2fma(Ay,  re[k], f2mul(Ax, im[k]))));
        re[k] = nr; im[k] = ni;
    }
}

// ---------------------------------------------------------------------------
// Passes. Wire w <-> amp bit (13-w).
// A: cube j{9..12}=amp{10..13}+lane: [carry (13,0)], w0..w3, w13, CNOT(0,1)(1,2)(2,3)
// B: cube j{5..8}=amp{6..9}: w4..w7, CNOT(3,4)pred,(4,5)(5,6)(6,7)
// C: cube j{0..3}=amp{1..4}, tid0=amp5: w8(shfl,+CNOT(7,8) fused), w9..w12,
//    CNOT(8,9)pred,(9,10)(10,11)(11,12),(12,13)lane; (13,0) carried out
// ---------------------------------------------------------------------------
__device__ __forceinline__ void pass_a(ull* reP, ull* imP, const float* gl,
                                       int tid, bool carry) {
    int pjb = swz4(tid);
    ull re[16], im[16];
    load16<9,10,11,12>(re, im, reP, imP, pjb);
    if (carry) carriedSwap(re, im);
    gateP<4,3>(re, im, (const ull*)(gl + 0*24));   // w0 (amp13)
    gateP<4,2>(re, im, (const ull*)(gl + 1*24));   // w1 (amp12)
    gateP<4,1>(re, im, (const ull*)(gl + 2*24));   // w2 (amp11)
    gateP<4,0>(re, im, (const ull*)(gl + 3*24));   // w3 (amp10)
    gateLaneAll(re, im, (const ull*)(gl + 13*24)); // w13 (amp0)
    cnotP<4,3,2>(re, im); cnotP<4,2,1>(re, im); cnotP<4,1,0>(re, im);
    store16<9,10,11,12>(re, im, reP, imP, pjb);
}
__device__ __forceinline__ void pass_b(ull* reP, ull* imP, const float* gl, int tid) {
    int base = (tid & 31) | ((tid >> 5) << 9);
    int pjb = swz4(base);
    ull re[16], im[16];
    load16<5,6,7,8>(re, im, reP, imP, pjb);
    gateP<4,3>(re, im, (const ull*)(gl + 4*24));   // w4 (amp9)
    gateP<4,2>(re, im, (const ull*)(gl + 5*24));   // w5 (amp8)
    gateP<4,1>(re, im, (const ull*)(gl + 6*24));   // w6 (amp7)
    gateP<4,0>(re, im, (const ull*)(gl + 7*24));   // w7 (amp6)
    cswapHalf<4,3>(re, im, (tid >> 5) & 1);        // CNOT(3,4): ctrl amp10=j9=tid5
    cnotP<4,3,2>(re, im); cnotP<4,2,1>(re, im); cnotP<4,1,0>(re, im);
    store16<5,6,7,8>(re, im, reP, imP, pjb);
}
__device__ __forceinline__ void pass_c(ull* reP, ull* imP, const float* gl,
                                       const float* g8, int tid) {
    int pjb = swz4(tid << 4);
    ull re[16], im[16];
    load16<0,1,2,3>(re, im, reP, imP, pjb);
    // w8 (amp5 = tid bit0) with CNOT(7,8) fused: sel = amp5 | (amp6<<1) = tid&3
    gateShfl(re, im, (const ull*)(g8 + (tid & 3) * 12));
    gateP<4,3>(re, im, (const ull*)(gl + 9*24));   // w9 (amp4)
    gateP<4,2>(re, im, (const ull*)(gl + 10*24));  // w10 (amp3)
    gateP<4,1>(re, im, (const ull*)(gl + 11*24));  // w11 (amp2)
    gateP<4,0>(re, im, (const ull*)(gl + 12*24));  // w12 (amp1)
    cswapHalf<4,3>(re, im, tid & 1);               // CNOT(8,9): ctrl amp5=tid0
    cnotP<4,3,2>(re, im); cnotP<4,2,1>(re, im); cnotP<4,1,0>(re, im);
    // CNOT(12,13): ctrl amp1 (cube bit0), tgt amp0 (lane)
#pragma unroll
    for (int k = 1; k < 16; k += 2) { re[k] = lswap(re[k]); im[k] = lswap(im[k]); }
    store16<0,1,2,3>(re, im, reP, imP, pjb);
    // CNOT(13,0) carried to next layer's pass A
}

// ---------------------------------------------------------------------------
// Kernel. SMEM (floats): re[16384] | im[16384] | gmat[42*24] | g8tab[3*4*12]
//                       | enc[28] | red[240]
// ---------------------------------------------------------------------------
__global__ void __launch_bounds__(NT, 1)
vqc_kernel(const float* __restrict__ x,    const float* __restrict__ w_in,
           const float* __restrict__ b_in, const float* __restrict__ wts,
           const float* __restrict__ w_out,const float* __restrict__ b_out,
           float* __restrict__ out)
{
    extern __shared__ float smem[];
    float* reF   = smem;
    float* imF   = smem + DIM;
    float* gmat  = smem + 2 * DIM;          // 1008
    float* g8tab = gmat + 42 * 24;          // 144
    float* enc   = g8tab + 144;             // 28
    float* red   = enc + 28;                // 240
    ull* reP = (ull*)reF;
    ull* imP = (ull*)imF;
    float2* ftab = (float2*)red;            // reuse red for init factor table (56 floats)

    const int b = blockIdx.x, tid = threadIdx.x;

    if (tid < NQ) {
        float acc = b_in[tid];
#pragma unroll
        for (int s2 = 0; s2 < SEQL; ++s2) acc += x[b*SEQL + s2] * w_in[tid*SEQL + s2];
        enc[2*tid]     = cospif(0.5f * acc);
        enc[2*tid + 1] = sinpif(0.5f * acc);
    }
    __syncthreads();

    // --- fused U = RZ*RY*RX per (layer, wire); layer1 folded; layer4 drops RZ
    if (tid < NQ * NL) {
        int i = tid % NQ, j = tid / NQ;
        const float* w = wts + (i*NL + j)*3;
        float cx = cosf(0.5f*w[0]), sx = sinf(0.5f*w[0]);
        float cy = cosf(0.5f*w[1]), sy = sinf(0.5f*w[1]);
        float cz = cosf(0.5f*w[2]), sz = sinf(0.5f*w[2]);
        if (j == 3) { cz = 1.f; sz = 0.f; }   // final-layer RZ is phase-only
        float2 m00 = make_float2( cy*cx,  sy*sx);
        float2 m01 = make_float2(-sy*cx, -cy*sx);
        float2 m10 = make_float2( sy*cx, -cy*sx);
        float2 m11 = make_float2( cy*cx, -sy*sx);
        float2 e0 = make_float2(cz, -sz), e1 = make_float2(cz, sz);
        float2 u00 = cmulf(e0, m00), u01 = cmulf(e0, m01);
        float2 u10 = cmulf(e1, m10), u11 = cmulf(e1, m11);
        if (j == 0) {
            float c = enc[2*i], s = enc[2*i+1];
            int t = 13 - i;
            ftab[t*2 + 0] = make_float2(u00.x*c + u01.x*s, u00.y*c + u01.y*s);
            ftab[t*2 + 1] = make_float2(u10.x*c + u11.x*s, u10.y*c + u11.y*s);
        } else if (i == 8) {
            // 4 row tables for shuffle gate: sel = amp5 | (amp6<<1)
            float2 Ca[4] = { u00, u11, u10, u01 };
            float2 Cb[4] = { u01, u10, u11, u00 };
#pragma unroll
            for (int s4 = 0; s4 < 4; ++s4) {
                float* r = g8tab + ((j-1)*4 + s4)*12;
                r[0]=Ca[s4].x; r[1]=Ca[s4].x;  r[2]=Ca[s4].y; r[3]=Ca[s4].y;
                r[4]=-Ca[s4].y; r[5]=-Ca[s4].y; r[6]=Cb[s4].x; r[7]=Cb[s4].x;
                r[8]=Cb[s4].y; r[9]=Cb[s4].y;  r[10]=-Cb[s4].y; r[11]=-Cb[s4].y;
            }
        } else {
            float* g = gmat + ((j-1)*NQ + i)*24;
            if (i < 13) {
                float c[12] = { u00.x, u00.y, -u00.y, u01.x, u01.y, -u01.y,
                                u10.x, u10.y, -u10.y, u11.x, u11.y, -u11.y };
#pragma unroll
                for (int q = 0; q < 12; ++q) { g[2*q] = c[q]; g[2*q+1] = c[q]; }
            } else {
                g[0] = u00.x;  g[1] = u11.x;
                g[2] = -u00.y; g[3] = -u11.y;
                g[4] = u00.y;  g[5] = u11.y;
                g[6] = u01.x;  g[7] = u10.x;
                g[8] = -u01.y; g[9] = -u10.y;
                g[10] = u01.y; g[11] = u10.y;
            }
        }
    }
    __syncthreads();

    // --- init: state AFTER layer 1 (ring folded via q = (p^(p>>1)) ^ ((p&1)*0x3000))
    {
        int ql = (tid ^ (tid >> 1)) & 0xFF;
        float2 lowp = make_float2(1.f, 0.f);
#pragma unroll
        for (int t = 0; t < 8; ++t)
            lowp = cmulf(lowp, ftab[t*2 + ((ql >> t) & 1)]);
        float2 F0[6], F1[6];
#pragma unroll
        for (int t = 0; t < 6; ++t) { F0[t] = ftab[(8+t)*2]; F1[t] = ftab[(8+t)*2+1]; }
        int t0 = tid & 1, t8 = (tid >> 8) & 1;
#pragma unroll
        for (int k = 0; k < DIM/NT; ++k) {
            int q8  = t8 ^ (k & 1);
            int q9  = (k ^ (k >> 1)) & 1;
            int q10 = ((k >> 1) ^ (k >> 2)) & 1;
            int q11 = ((k >> 2) ^ (k >> 3)) & 1;
            int q12 = (((k >> 3) ^ (k >> 4)) & 1) ^ t0;
            int q13 = ((k >> 4) & 1) ^ t0;
            float2 p = lowp;
            p = cmulf(p, q8  ? F1[0] : F0[0]);
            p = cmulf(p, q9  ? F1[1] : F0[1]);
            p = cmulf(p, q10 ? F1[2] : F0[2]);
            p = cmulf(p, q11 ? F1[3] : F0[3]);
            p = cmulf(p, q12 ? F1[4] : F0[4]);
            p = cmulf(p, q13 ? F1[5] : F0[5]);
            int idx = tid + NT*k;
            int a = 2*swz4(idx >> 1) + (idx & 1);
            reF[a] = p.x; imF[a] = p.y;
        }
    }
    __syncthreads();

    // --- layers 2, 3 ---
#pragma unroll 1
    for (int jl = 0; jl < 2; ++jl) {
        const float* gl = gmat + jl * NQ * 24;
        const float* g8 = g8tab + jl * 48;
        pass_a(reP, imP, gl, tid, jl > 0);  __syncthreads();
        pass_b(reP, imP, gl, tid);          __syncthreads();
        pass_c(reP, imP, gl, g8, tid);      __syncthreads();
    }

    // --- layer 4: A(carry), B, then C fused with readout (CNOT chain folded) ---
    {
        const float* gl = gmat + 2 * NQ * 24;
        const float* g8 = g8tab + 2 * 48;
        pass_a(reP, imP, gl, tid, true);  __syncthreads();
        pass_b(reP, imP, gl, tid);        __syncthreads();

        int pjb = swz4(tid << 4);
        ull re[16], im[16];
        load16<0,1,2,3>(re, im, reP, imP, pjb);
        gateShfl(re, im, (const ull*)(g8 + (tid & 1) * 12));  // w8, no CNOT fusion
        gateP<4,3>(re, im, (const ull*)(gl + 9*24));
        gateP<4,2>(re, im, (const ull*)(gl + 10*24));
        gateP<4,1>(re, im, (const ull*)(gl + 11*24));
        gateP<4,0>(re, im, (const ull*)(gl + 12*24));

        // Readout with residual-chain relabel for CNOT(7,8)..(12,13),(13,0).
        // Register-space bits: lane=amp0(wire13), k0..k3=amp1..4(wires 12..9),
        // tid0..tid8 = amp5..amp13 (wires 8..0).
        // Post-chain wire bits: w in 1..7 -> unchanged (tid_{8-w});
        // w8 -> tid0^tid1; w9 -> k3^tid0^tid1; w10 -> k2^k3^t01;
        // w11 -> k1^k2^k3^t01; w12 -> popc(k)^t01; w13 -> lane^popc(k)^t01;
        // w0 -> tid8 ^ (w13 bit).
        ull accP = 0, acc9 = 0, acc10 = 0, acc11 = 0, acc12 = 0;
        const ull NEG1 = 0xBF800000BF800000ull;
#pragma unroll
        for (int k = 0; k < 16; ++k) {
            ull p = f2fma(im[k], im[k], f2mul(re[k], re[k]));
            accP = f2add(accP, p);
            int k3 = (k >> 3) & 1;
            int k23 = ((k >> 2) ^ (k >> 3)) & 1;
            int k123 = ((k >> 1) ^ (k >> 2) ^ (k >> 3)) & 1;
            int kpar = __popc(k) & 1;
            acc9  = k3   ? f2fma(p, NEG1, acc9)  : f2add(acc9,  p);
            acc10 = k23  ? f2fma(p, NEG1, acc10) : f2add(acc10, p);
            acc11 = k123 ? f2fma(p, NEG1, acc11) : f2add(acc11, p);
            acc12 = kpar ? f2fma(p, NEG1, acc12) : f2add(acc12, p);
        }
        float z[NQ];
        {
            float Pl, Ph;  upk(accP, Pl, Ph);   float Ps = Pl + Ph;
            float l9, h9;  upk(acc9, l9, h9);
            float l10,h10; upk(acc10,l10,h10);
            float l11,h11; upk(acc11,l11,h11);
            float l12,h12; upk(acc12,l12,h12);
            int t01 = (tid ^ (tid >> 1)) & 1;           // tid0 ^ tid1
            float f5 = t01 ? -1.f : 1.f;
            z[1] = (tid & 128) ? -Ps : Ps;   // wire1 = tid7
            z[2] = (tid & 64)  ? -Ps : Ps;   // wire2 = tid6
            z[3] = (tid & 32)  ? -Ps : Ps;   // wire3 = tid5
            z[4] = (tid & 16)  ? -Ps : Ps;   // wire4 = tid4
            z[5] = (tid & 8)   ? -Ps : Ps;   // wire5 = tid3
            z[6] = (tid & 4)   ? -Ps : Ps;   // wire6 = tid2
            z[7] = (tid & 2)   ? -Ps : Ps;   // wire7 = tid1
            z[8] = t01 ? -Ps : Ps;           // wire8 = tid0^tid1
            z[9]  = f5 * (l9  + h9);
            z[10] = f5 * (l10 + h10);
            z[11] = f5 * (l11 + h11);
            z[12] = f5 * (l12 + h12);
            z[13] = f5 * (l12 - h12);
            z[0]  = (tid & 256) ? -z[13] : z[13];   // wire0 adds tid8
        }

#pragma unroll
        for (int w = 0; w < NQ; ++w)
#pragma unroll
            for (int o = 16; o; o >>= 1)
                z[w] += __shfl_xor_sync(0xffffffffu, z[w], o);

        __syncthreads();   // red no longer used as ftab beyond init
        if ((tid & 31) == 0) {
            int wr = tid >> 5;
#pragma unroll
            for (int w = 0; w < NQ; ++w) red[wr*NQ + w] = z[w];
        }
        __syncthreads();
        if (tid < NQ) {
            float s = 0.f;
#pragma unroll
            for (int wr = 0; wr < NT/32; ++wr) s += red[wr*NQ + tid];
            red[224 + tid] = s * w_out[tid];
        }
        __syncthreads();
        if (tid == 0) {
            float o = b_out[0];
#pragma unroll
            for (int w = 0; w < NQ; ++w) o += red[224 + w];
            out[b] = o;
        }
    }
}

// ---------------------------------------------------------------------------
extern "C" void kernel_launch(void* const* d_in, const int* in_sizes, int n_in,
                              void* d_out, int out_size)
{
    const float* x     = (const float*)d_in[0];
    const float* w_in  = (const float*)d_in[1];
    const float* b_in  = (const float*)d_in[2];
    const float* wts   = (const float*)d_in[3];
    const float* w_out = (const float*)d_in[4];
    const float* b_out = (const float*)d_in[5];
    float* out = (float*)d_out;

    const int B = in_sizes[0] / SEQL;                       // 1024
    const int smem = (2*DIM + 42*24 + 144 + 28 + 240) * (int)sizeof(float);

    cudaFuncSetAttribute(vqc_kernel, cudaFuncAttributeMaxDynamicSharedMemorySize, smem);
    vqc_kernel<<<B, NT, smem>>>(x, w_in, b_in, wts, w_out, b_out, out);
}